// round 12
// baseline (speedup 1.0000x reference)
#include <cuda_runtime.h>
#include <cuda_fp16.h>
#include <math.h>
#include <stdint.h>

#define EMBED 1024
#define HEADS 16
#define DKH 64
#define BATCH 2
#define SEQ 2048
#define MTOT (BATCH * SEQ)   // 4096
#define WSZ (EMBED * EMBED)  // 1048576

// ---- fp16 GEMM tiling: CTA 128x128, BK=64, 8 warps (2x4), warp tile 64x32 ----
#define NCH2 16            // 1024/64 k-chunks
#define GASTR 144          // A smem row stride BYTES (72 halves)
#define GBSTR 272          // B smem row stride BYTES (136 halves)
#define GABYTES (128 * GASTR)       // 18432
#define GBBYTES (64 * GBSTR)        // 17408
#define GSTAGE (GABYTES + GBBYTES)  // 35840
#define GSMEM 73728                 // max(2*GSTAGE=71680, epilogue 8*64*36*4)

// ---- flash fp16 smem (bytes): KV tiles 128x64 halves, stride 144B, 2 stages ----
#define FST 144
#define FK0B 0
#define FK1B 18432
#define FV0B 36864
#define FV1B 55296
#define FQPB 73728
#define FSMEMB (FQPB + 128 * FST)  // 92160

// Scratch (allocation-free rule: __device__ globals)
__device__ __half g_x16[(size_t)MTOT * EMBED];
__device__ __half g_w16[(size_t)4 * WSZ];
__device__ __half g_q[(size_t)BATCH * HEADS * SEQ * DKH];
__device__ __half g_k[(size_t)BATCH * HEADS * SEQ * DKH];
__device__ __half g_v[(size_t)BATCH * HEADS * SEQ * DKH];
__device__ __half g_attn[(size_t)MTOT * EMBED];
__device__ float2 g_rope[(size_t)SEQ * 32];

// ---------------------------------------------------------------------------
// helpers
// ---------------------------------------------------------------------------
__device__ __forceinline__ uint32_t su32(const void* p) {
    uint32_t a;
    asm("{ .reg .u64 t; cvta.to.shared.u64 t, %1; cvt.u32.u64 %0, t; }"
        : "=r"(a) : "l"(p));
    return a;
}

__device__ __forceinline__ void cp16(uint32_t dst, const void* src) {
    asm volatile("cp.async.cg.shared.global [%0], [%1], 16;" :: "r"(dst), "l"(src));
}

__device__ __forceinline__ void ldsm4(uint32_t* r, uint32_t a) {
    asm volatile("ldmatrix.sync.aligned.m8n8.x4.shared.b16 {%0,%1,%2,%3}, [%4];"
                 : "=r"(r[0]), "=r"(r[1]), "=r"(r[2]), "=r"(r[3]) : "r"(a));
}

__device__ __forceinline__ void ldsm4t(uint32_t* r, uint32_t a) {
    asm volatile("ldmatrix.sync.aligned.m8n8.x4.trans.shared.b16 {%0,%1,%2,%3}, [%4];"
                 : "=r"(r[0]), "=r"(r[1]), "=r"(r[2]), "=r"(r[3]) : "r"(a));
}

__device__ __forceinline__ void mma16(float* d, const uint32_t* a, const uint32_t* b) {
    asm volatile(
        "mma.sync.aligned.m16n8k16.row.col.f32.f16.f16.f32 "
        "{%0,%1,%2,%3}, {%4,%5,%6,%7}, {%8,%9}, {%0,%1,%2,%3};"
        : "+f"(d[0]), "+f"(d[1]), "+f"(d[2]), "+f"(d[3])
        : "r"(a[0]), "r"(a[1]), "r"(a[2]), "r"(a[3]), "r"(b[0]), "r"(b[1]));
}

__device__ __forceinline__ uint32_t packh2(float lo, float hi) {
    __half2 h = __floats2half2_rn(lo, hi);
    return *(uint32_t*)&h;
}

union H2U8 {
    __half2 h[2];
    uint2 u;
};

// ---------------------------------------------------------------------------
// prep: RoPE table + fused fp32->fp16 conversion (4 float4s per thread, MLP=4)
// ---------------------------------------------------------------------------
__global__ void rope_table_kernel() {
    int idx = blockIdx.x * 256 + threadIdx.x;
    int s = idx >> 5, p = idx & 31;
    double inv = 1.0 / pow(10000.0, (double)(2 * p) / 64.0);
    float ang = (float)s * (float)inv;
    g_rope[idx] = make_float2(cosf(ang), sinf(ang));
}

#define CVT_TOTAL4 (MTOT * EMBED / 4 + WSZ)  // 2097152 float4 units
#define CVT_STRIDE (CVT_TOTAL4 / 4)          // 524288

__global__ void __launch_bounds__(256) cvt_fp16(const float* __restrict__ x,
                                                const float* __restrict__ wq,
                                                const float* __restrict__ wk,
                                                const float* __restrict__ wv,
                                                const float* __restrict__ wo) {
    const int XN4 = MTOT * EMBED / 4;
    int base = blockIdx.x * 256 + threadIdx.x;
#pragma unroll
    for (int it = 0; it < 4; it++) {
        int i4 = base + it * CVT_STRIDE;
        const float* src;
        __half* dst;
        size_t off;
        if (i4 < XN4) {
            src = x;
            dst = g_x16;
            off = (size_t)i4 * 4;
        } else {
            int r = i4 - XN4;
            int wsel = r >> 18;  // WSZ/4 = 2^18
            int o4 = r & ((1 << 18) - 1);
            src = wsel == 0 ? wq : (wsel == 1 ? wk : (wsel == 2 ? wv : wo));
            dst = g_w16 + (size_t)wsel * WSZ;
            off = (size_t)o4 * 4;
        }
        float4 v = *(const float4*)(src + off);
        H2U8 pk;
        pk.h[0] = __floats2half2_rn(v.x, v.y);
        pk.h[1] = __floats2half2_rn(v.z, v.w);
        *(uint2*)(dst + off) = pk.u;
    }
}

// ---------------------------------------------------------------------------
// fp16 GEMM: C[4096,1024] = A @ W (both fp16, W row-major [K][N]).
// CTA 128x128, BK=64, 2-stage cp.async, ldmatrix fragments, fp32 accum.
// MODE 1: z selects wq/wk/wv; RoPE for z<2; scatter fp16 to [B,H,S,DKH].
// MODE 0: wo projection; fp32 [M][N] store to out.
// ---------------------------------------------------------------------------
template <int MODE>
__global__ void __launch_bounds__(256) gemm_h(const __half* __restrict__ A,
                                              const __half* __restrict__ w0,
                                              const __half* __restrict__ w1,
                                              const __half* __restrict__ w2,
                                              void* __restrict__ d0,
                                              void* __restrict__ d1,
                                              void* __restrict__ d2) {
    extern __shared__ __align__(16) char smc[];
    float* sm = (float*)smc;

    const int tid = threadIdx.x;
    const int lane = tid & 31, wid = tid >> 5;
    const int wm = wid >> 2, wn = wid & 3;
    const int gr = lane >> 2, gc = lane & 3;
    const int n0 = blockIdx.x * 128;
    const int m0 = blockIdx.y * 128;

    const __half* W;
    void* dst;
    int rope;
    if (MODE == 1) {
        int z = blockIdx.z;
        W = z == 0 ? w0 : (z == 1 ? w1 : w2);
        dst = z == 0 ? d0 : (z == 1 ? d1 : d2);
        rope = (z < 2);
    } else {
        W = w0;
        dst = d0;
        rope = 0;
    }

    const uint32_t smb = su32(smc);

    auto fill = [&](int s, int kc) {
        uint32_t ab = smb + (uint32_t)s * GSTAGE;
        uint32_t bb = ab + GABYTES;
#pragma unroll
        for (int it = 0; it < 4; it++) {
            int idx = tid + it * 256;
            int r = idx >> 3, c = idx & 7;
            cp16(ab + (uint32_t)(r * GASTR + c * 16),
                 A + (size_t)(m0 + r) * EMBED + kc + c * 8);
        }
#pragma unroll
        for (int it = 0; it < 4; it++) {
            int idx = tid + it * 256;
            int r = idx >> 4, c = idx & 15;
            cp16(bb + (uint32_t)(r * GBSTR + c * 16),
                 W + (size_t)(kc + r) * EMBED + n0 + c * 8);
        }
        asm volatile("cp.async.commit_group;" ::: "memory");
    };

    float acc[4][4][4];
#pragma unroll
    for (int mi = 0; mi < 4; mi++)
#pragma unroll
        for (int ni = 0; ni < 4; ni++)
#pragma unroll
            for (int r = 0; r < 4; r++) acc[mi][ni][r] = 0.f;

    fill(0, 0);

    const int a_row = (lane & 15);
    const int a_kh = (lane >> 4) * 8;
    const int b_kr = ((lane >> 3) & 1) * 8 + (lane & 7);
    const int b_nh = ((lane >> 4) & 1) * 8;

    for (int i = 0; i < NCH2; i++) {
        if (i + 1 < NCH2) {
            fill((i + 1) & 1, (i + 1) * 64);
            asm volatile("cp.async.wait_group 1;" ::: "memory");
        } else {
            asm volatile("cp.async.wait_group 0;" ::: "memory");
        }
        __syncthreads();

        const uint32_t Asb = smb + (uint32_t)(i & 1) * GSTAGE;
        const uint32_t Bsb = Asb + GABYTES;

#pragma unroll
        for (int ks = 0; ks < 4; ks++) {
            const int kb = ks * 16;
            uint32_t af[4][4], bfr[2][4];
#pragma unroll
            for (int mi = 0; mi < 4; mi++)
                ldsm4(af[mi], Asb + (uint32_t)((wm * 64 + mi * 16 + a_row) * GASTR +
                                               (kb + a_kh) * 2));
#pragma unroll
            for (int p = 0; p < 2; p++)
                ldsm4t(bfr[p], Bsb + (uint32_t)((kb + b_kr) * GBSTR +
                                                (wn * 32 + p * 16 + b_nh) * 2));
#pragma unroll
            for (int mi = 0; mi < 4; mi++)
#pragma unroll
                for (int ni = 0; ni < 4; ni++)
                    mma16(acc[mi][ni], af[mi], &bfr[ni >> 1][(ni & 1) * 2]);
        }
        __syncthreads();
    }

    // ---- epilogue ----
    if (rope) {
#pragma unroll
        for (int mi = 0; mi < 4; mi++)
#pragma unroll
            for (int h2 = 0; h2 < 2; h2++) {
                int row = m0 + wm * 64 + mi * 16 + gr + h2 * 8;
                int s = row & (SEQ - 1);
#pragma unroll
                for (int ni = 0; ni < 4; ni++) {
                    int col = n0 + wn * 32 + ni * 8 + gc * 2;
                    int p = (col & 63) >> 1;
                    float2 cs = g_rope[(size_t)s * 32 + p];
                    float e = acc[mi][ni][h2 * 2 + 0];
                    float o = acc[mi][ni][h2 * 2 + 1];
                    acc[mi][ni][h2 * 2 + 0] = e * cs.x - o * cs.y;
                    acc[mi][ni][h2 * 2 + 1] = o * cs.x + e * cs.y;
                }
            }
    }

    float* stg = sm + wid * (64 * 36);
#pragma unroll
    for (int mi = 0; mi < 4; mi++)
#pragma unroll
        for (int ni = 0; ni < 4; ni++)
#pragma unroll
            for (int h2 = 0; h2 < 2; h2++) {
                int rl = mi * 16 + gr + h2 * 8;
                int cl = ni * 8 + gc * 2;
                *(float2*)&stg[rl * 36 + cl] =
                    make_float2(acc[mi][ni][h2 * 2], acc[mi][ni][h2 * 2 + 1]);
            }
    __syncwarp();

    const int lr = lane >> 3, c4 = lane & 7;
    if (MODE == 0) {
        float* df = (float*)dst;
#pragma unroll
        for (int it = 0; it < 16; it++) {
            int rl = it * 4 + lr;
            float4 v = *(float4*)&stg[rl * 36 + c4 * 4];
            int row = m0 + wm * 64 + rl;
            *(float4*)&df[(size_t)row * EMBED + n0 + wn * 32 + c4 * 4] = v;
        }
    } else {
        __half* dh = (__half*)dst;
        const int ncol = n0 + wn * 32;
        const int h = ncol >> 6, dbase = ncol & 63;
#pragma unroll
        for (int it = 0; it < 16; it++) {
            int rl = it * 4 + lr;
            float4 v = *(float4*)&stg[rl * 36 + c4 * 4];
            int row = m0 + wm * 64 + rl;
            int b = row >> 11;
            int s = row & (SEQ - 1);
            H2U8 pk;
            pk.h[0] = __floats2half2_rn(v.x, v.y);
            pk.h[1] = __floats2half2_rn(v.z, v.w);
            *(uint2*)&dh[(((size_t)(b * HEADS + h)) * SEQ + s) * DKH + dbase + c4 * 4] = pk.u;
        }
    }
}

// ---------------------------------------------------------------------------
// fp16 tensor-core flash attention, causal, no online max, P fragments built
// entirely in registers (D-frag layout == A-frag layout; no smem round-trip).
// CTA: 128 q-rows, 8 warps; KV tiles of 128 rows double-buffered, two
// 64-column halves per tile; per-warp column-group skip on the diagonal.
// ---------------------------------------------------------------------------
__global__ void __launch_bounds__(256) flash_h(const __half* __restrict__ Q,
                                               const __half* __restrict__ Kk,
                                               const __half* __restrict__ V,
                                               __half* __restrict__ Out) {
    extern __shared__ __align__(16) char fsb[];
    const int tid = threadIdx.x;
    const int lane = tid & 31, w = tid >> 5;
    const int gr = lane >> 2, gc = lane & 3;
    const int qi = gridDim.x - 1 - blockIdx.x;  // long blocks launch first
    const int bh = blockIdx.y;
    const int nt = qi + 1;  // kv tiles of 128

    const __half* Qb = Q + ((size_t)bh * SEQ + (size_t)qi * 128) * DKH;
    const __half* Kb = Kk + (size_t)bh * SEQ * DKH;
    const __half* Vb = V + (size_t)bh * SEQ * DKH;

    const uint32_t fb = su32(fsb);

    auto fillkv = [&](int buf, int j) {
        uint32_t kd = fb + (buf ? FK1B : FK0B);
        uint32_t vd = fb + (buf ? FV1B : FV0B);
        const __half* ks = Kb + (size_t)j * 128 * DKH;
        const __half* vs = Vb + (size_t)j * 128 * DKH;
#pragma unroll
        for (int it = 0; it < 4; it++) {
            int idx = tid + it * 256;
            int r = idx >> 3, c = idx & 7;
            cp16(kd + (uint32_t)(r * FST + c * 16), ks + r * 64 + c * 8);
        }
#pragma unroll
        for (int it = 0; it < 4; it++) {
            int idx = tid + it * 256;
            int r = idx >> 3, c = idx & 7;
            cp16(vd + (uint32_t)(r * FST + c * 16), vs + r * 64 + c * 8);
        }
        asm volatile("cp.async.commit_group;" ::: "memory");
    };

    {  // Q tile (128x64)
        uint32_t qd = fb + FQPB;
#pragma unroll
        for (int it = 0; it < 4; it++) {
            int idx = tid + it * 256;
            int r = idx >> 3, c = idx & 7;
            cp16(qd + (uint32_t)(r * FST + c * 16), Qb + r * 64 + c * 8);
        }
    }
    fillkv(0, 0);
    if (nt > 1) fillkv(1, 1);

    if (nt > 1)
        asm volatile("cp.async.wait_group 1;" ::: "memory");
    else
        asm volatile("cp.async.wait_group 0;" ::: "memory");
    __syncthreads();

    // ldmatrix address components
    const int a_row = (lane & 15);
    const int a_kh = (lane >> 4) * 8;
    const int b_kr = ((lane >> 3) & 1) * 8 + (lane & 7);
    const int b_nh = ((lane >> 4) & 1) * 8;
    const int k_nr = ((lane >> 4) & 1) * 8 + (lane & 7);
    const int k_kh = ((lane >> 3) & 1) * 8;

    // Q fragments persist in registers
    uint32_t qf[4][4];
#pragma unroll
    for (int ks = 0; ks < 4; ks++)
        ldsm4(qf[ks], fb + FQPB + (uint32_t)((w * 16 + a_row) * FST + (ks * 16 + a_kh) * 2));

    float liA = 0.f, liB = 0.f;
    float oacc[8][4];
#pragma unroll
    for (int n8 = 0; n8 < 8; n8++)
#pragma unroll
        for (int r = 0; r < 4; r++) oacc[n8][r] = 0.f;

    const int wrow = qi * 128 + w * 16;

    for (int j = 0; j < nt; j++) {
        if (j <= nt - 2)
            asm volatile("cp.async.wait_group 1;" ::: "memory");
        else
            asm volatile("cp.async.wait_group 0;" ::: "memory");
        __syncthreads();

        const uint32_t Ksb = fb + ((j & 1) ? FK1B : FK0B);
        const uint32_t Vsb = fb + ((j & 1) ? FV1B : FV0B);

#pragma unroll
        for (int half = 0; half < 2; half++) {
            const int colbase = j * 128 + half * 64;
            if (colbase > wrow + 15) break;  // rest of tile fully masked

            const uint32_t Kh = Ksb + (uint32_t)(half * 64 * FST);
            const uint32_t Vh = Vsb + (uint32_t)(half * 64 * FST);
            const bool diag = (colbase + 63 > wrow);

            // P fragments built in registers: pf[pg] covers S cols pg*16..+15
            uint32_t pf[4][4];

#pragma unroll
            for (int pg = 0; pg < 4; pg++) {
                if (diag && colbase + pg * 16 > wrow + 15) {
                    // fully masked column group for this warp
                    pf[pg][0] = pf[pg][1] = pf[pg][2] = pf[pg][3] = 0u;
                    continue;
                }
                float s0[4] = {0.f, 0.f, 0.f, 0.f};
                float s1[4] = {0.f, 0.f, 0.f, 0.f};
#pragma unroll
                for (int ks = 0; ks < 4; ks++) {
                    uint32_t kf[4];
                    ldsm4(kf, Kh + (uint32_t)((pg * 16 + k_nr) * FST + (ks * 16 + k_kh) * 2));
                    mma16(s0, qf[ks], &kf[0]);
                    mma16(s1, qf[ks], &kf[2]);
                }
                float p00, p01, p02, p03, p10, p11, p12, p13;
                if (diag) {
                    int r0 = wrow + gr;
                    int c0 = colbase + pg * 16 + 2 * gc;
                    int c1 = c0 + 8;
                    p00 = (c0 > r0) ? 0.f : __expf(s0[0] * 0.125f);
                    p01 = (c0 + 1 > r0) ? 0.f : __expf(s0[1] * 0.125f);
                    p02 = (c0 > r0 + 8) ? 0.f : __expf(s0[2] * 0.125f);
                    p03 = (c0 + 1 > r0 + 8) ? 0.f : __expf(s0[3] * 0.125f);
                    p10 = (c1 > r0) ? 0.f : __expf(s1[0] * 0.125f);
                    p11 = (c1 + 1 > r0) ? 0.f : __expf(s1[1] * 0.125f);
                    p12 = (c1 > r0 + 8) ? 0.f : __expf(s1[2] * 0.125f);
                    p13 = (c1 + 1 > r0 + 8) ? 0.f : __expf(s1[3] * 0.125f);
                } else {
                    p00 = __expf(s0[0] * 0.125f);
                    p01 = __expf(s0[1] * 0.125f);
                    p02 = __expf(s0[2] * 0.125f);
                    p03 = __expf(s0[3] * 0.125f);
                    p10 = __expf(s1[0] * 0.125f);
                    p11 = __expf(s1[1] * 0.125f);
                    p12 = __expf(s1[2] * 0.125f);
                    p13 = __expf(s1[3] * 0.125f);
                }
                liA += p00 + p01 + p10 + p11;
                liB += p02 + p03 + p12 + p13;
                // A-frag packing: a0 = row gr k-lo, a1 = row gr+8 k-lo,
                //                 a2 = row gr k-hi, a3 = row gr+8 k-hi
                pf[pg][0] = packh2(p00, p01);
                pf[pg][1] = packh2(p02, p03);
                pf[pg][2] = packh2(p10, p11);
                pf[pg][3] = packh2(p12, p13);
            }

            // O += P V (pf[kc] is the A-frag for P's k-chunk kc)
#pragma unroll
            for (int kc = 0; kc < 4; kc++) {
                if (diag && colbase + kc * 16 > wrow + 15) continue;  // pf zero
                const int kb = kc * 16;
#pragma unroll
                for (int p = 0; p < 4; p++) {
                    uint32_t vf[4];
                    ldsm4t(vf, Vh + (uint32_t)((kb + b_kr) * FST + (p * 16 + b_nh) * 2));
                    mma16(oacc[2 * p], pf[kc], &vf[0]);
                    mma16(oacc[2 * p + 1], pf[kc], &vf[2]);
                }
            }
        }

        __syncthreads();  // all warps done with this KV buffer
        if (j + 2 < nt) fillkv(j & 1, j + 2);
    }

    // final row-sum reduction + normalize + write [B,S,E]
    liA += __shfl_xor_sync(0xffffffffu, liA, 1);
    liA += __shfl_xor_sync(0xffffffffu, liA, 2);
    liB += __shfl_xor_sync(0xffffffffu, liB, 1);
    liB += __shfl_xor_sync(0xffffffffu, liB, 2);

    const int b = bh >> 4, h = bh & 15;
    const int row = wrow + gr;
    float invA = 1.f / liA, invB = 1.f / liB;
    __half* o0 = Out + ((size_t)b * SEQ + row) * EMBED + h * 64;
    __half* o1 = Out + ((size_t)b * SEQ + row + 8) * EMBED + h * 64;
#pragma unroll
    for (int n8 = 0; n8 < 8; n8++) {
        *(__half2*)&o0[n8 * 8 + 2 * gc] =
            __floats2half2_rn(oacc[n8][0] * invA, oacc[n8][1] * invA);
        *(__half2*)&o1[n8 * 8 + 2 * gc] =
            __floats2half2_rn(oacc[n8][2] * invB, oacc[n8][3] * invB);
    }
}

extern "C" void kernel_launch(void* const* d_in, const int* in_sizes, int n_in,
                              void* d_out, int out_size) {
    (void)in_sizes;
    (void)n_in;
    (void)out_size;
    const float* x = (const float*)d_in[0];
    const float* wq = (const float*)d_in[1];
    const float* wk = (const float*)d_in[2];
    const float* wv = (const float*)d_in[3];
    const float* wo = (const float*)d_in[4];
    float* out = (float*)d_out;

    __half *x16, *w16, *q, *k, *v, *attn;
    cudaGetSymbolAddress((void**)&x16, g_x16);
    cudaGetSymbolAddress((void**)&w16, g_w16);
    cudaGetSymbolAddress((void**)&q, g_q);
    cudaGetSymbolAddress((void**)&k, g_k);
    cudaGetSymbolAddress((void**)&v, g_v);
    cudaGetSymbolAddress((void**)&attn, g_attn);

    cudaFuncSetAttribute(gemm_h<1>, cudaFuncAttributeMaxDynamicSharedMemorySize, GSMEM);
    cudaFuncSetAttribute(gemm_h<0>, cudaFuncAttributeMaxDynamicSharedMemorySize, GSMEM);
    cudaFuncSetAttribute(flash_h, cudaFuncAttributeMaxDynamicSharedMemorySize, FSMEMB);

    rope_table_kernel<<<SEQ * 32 / 256, 256>>>();
    cvt_fp16<<<CVT_STRIDE / 256, 256>>>(x, wq, wk, wv, wo);
    gemm_h<1><<<dim3(EMBED / 128, MTOT / 128, 3), 256, GSMEM>>>(
        x16, w16, w16 + WSZ, w16 + 2 * WSZ, q, k, v);
    flash_h<<<dim3(SEQ / 128, BATCH * HEADS), 256, FSMEMB>>>(q, k, v, attn);
    gemm_h<0><<<dim3(EMBED / 128, MTOT / 128, 1), 256, GSMEM>>>(
        attn, w16 + 3 * WSZ, nullptr, nullptr, out, nullptr, nullptr);
}

// round 13
// speedup vs baseline: 1.0113x; 1.0113x over previous
#include <cuda_runtime.h>
#include <cuda_fp16.h>
#include <math.h>
#include <stdint.h>

#define EMBED 1024
#define HEADS 16
#define DKH 64
#define BATCH 2
#define SEQ 2048
#define MTOT (BATCH * SEQ)   // 4096
#define WSZ (EMBED * EMBED)  // 1048576

// ---- fp16 GEMM tiling: CTA 128x128, BK=64, 8 warps (2x4), warp tile 64x32 ----
#define NCH2 16            // 1024/64 k-chunks
#define GASTR 144          // A smem row stride BYTES (72 halves)
#define GBSTR 272          // B smem row stride BYTES (136 halves)
#define GABYTES (128 * GASTR)       // 18432
#define GBBYTES (64 * GBSTR)        // 17408
#define GSTAGE (GABYTES + GBBYTES)  // 35840
#define GSMEM 73728                 // max(2*GSTAGE=71680, epilogue 8*64*36*4)

// ---- flash fp16 smem (bytes): 2-stage KV tiles 128x64 halves, stride 144B.
//      Q staged through V0 in the prologue; no dedicated Q/P region. ----
#define FST 144
#define FK0B 0
#define FK1B 18432
#define FV0B 36864
#define FV1B 55296
#define FSMEMB 73728  // 3 CTAs/SM

// Scratch (allocation-free rule: __device__ globals)
__device__ __half g_x16[(size_t)MTOT * EMBED];
__device__ __half g_w16[(size_t)4 * WSZ];
__device__ __half g_q[(size_t)BATCH * HEADS * SEQ * DKH];
__device__ __half g_k[(size_t)BATCH * HEADS * SEQ * DKH];
__device__ __half g_v[(size_t)BATCH * HEADS * SEQ * DKH];
__device__ __half g_attn[(size_t)MTOT * EMBED];
__device__ float2 g_rope[(size_t)SEQ * 32];

// ---------------------------------------------------------------------------
// helpers
// ---------------------------------------------------------------------------
__device__ __forceinline__ uint32_t su32(const void* p) {
    uint32_t a;
    asm("{ .reg .u64 t; cvta.to.shared.u64 t, %1; cvt.u32.u64 %0, t; }"
        : "=r"(a) : "l"(p));
    return a;
}

__device__ __forceinline__ void cp16(uint32_t dst, const void* src) {
    asm volatile("cp.async.cg.shared.global [%0], [%1], 16;" :: "r"(dst), "l"(src));
}

__device__ __forceinline__ void ldsm4(uint32_t* r, uint32_t a) {
    asm volatile("ldmatrix.sync.aligned.m8n8.x4.shared.b16 {%0,%1,%2,%3}, [%4];"
                 : "=r"(r[0]), "=r"(r[1]), "=r"(r[2]), "=r"(r[3]) : "r"(a));
}

__device__ __forceinline__ void ldsm4t(uint32_t* r, uint32_t a) {
    asm volatile("ldmatrix.sync.aligned.m8n8.x4.trans.shared.b16 {%0,%1,%2,%3}, [%4];"
                 : "=r"(r[0]), "=r"(r[1]), "=r"(r[2]), "=r"(r[3]) : "r"(a));
}

__device__ __forceinline__ void mma16(float* d, const uint32_t* a, const uint32_t* b) {
    asm volatile(
        "mma.sync.aligned.m16n8k16.row.col.f32.f16.f16.f32 "
        "{%0,%1,%2,%3}, {%4,%5,%6,%7}, {%8,%9}, {%0,%1,%2,%3};"
        : "+f"(d[0]), "+f"(d[1]), "+f"(d[2]), "+f"(d[3])
        : "r"(a[0]), "r"(a[1]), "r"(a[2]), "r"(a[3]), "r"(b[0]), "r"(b[1]));
}

__device__ __forceinline__ uint32_t packh2(float lo, float hi) {
    __half2 h = __floats2half2_rn(lo, hi);
    return *(uint32_t*)&h;
}

union H2U8 {
    __half2 h[2];
    uint2 u;
};

// ---------------------------------------------------------------------------
// prep: RoPE table + fused fp32->fp16 conversion (R11-validated form)
// ---------------------------------------------------------------------------
__global__ void rope_table_kernel() {
    int idx = blockIdx.x * 256 + threadIdx.x;
    int s = idx >> 5, p = idx & 31;
    double inv = 1.0 / pow(10000.0, (double)(2 * p) / 64.0);
    float ang = (float)s * (float)inv;
    g_rope[idx] = make_float2(cosf(ang), sinf(ang));
}

__global__ void __launch_bounds__(256) cvt_fp16(const float* __restrict__ x,
                                                const float* __restrict__ wq,
                                                const float* __restrict__ wk,
                                                const float* __restrict__ wv,
                                                const float* __restrict__ wo) {
    const int XN4 = MTOT * EMBED / 4;
    int i4 = blockIdx.x * 256 + threadIdx.x;
    const float* src;
    __half* dst;
    size_t off;
    if (i4 < XN4) {
        src = x;
        dst = g_x16;
        off = (size_t)i4 * 4;
    } else {
        int r = i4 - XN4;
        int wsel = r >> 18;  // WSZ/4 = 2^18
        int o4 = r & ((1 << 18) - 1);
        src = wsel == 0 ? wq : (wsel == 1 ? wk : (wsel == 2 ? wv : wo));
        dst = g_w16 + (size_t)wsel * WSZ;
        off = (size_t)o4 * 4;
    }
    float4 v = *(const float4*)(src + off);
    H2U8 pk;
    pk.h[0] = __floats2half2_rn(v.x, v.y);
    pk.h[1] = __floats2half2_rn(v.z, v.w);
    *(uint2*)(dst + off) = pk.u;
}

// ---------------------------------------------------------------------------
// fp16 GEMM: C[4096,1024] = A @ W (both fp16, W row-major [K][N]).
// CTA 128x128, BK=64, 2-stage cp.async, ldmatrix fragments, fp32 accum.
// MODE 1: z selects wq/wk/wv; RoPE for z<2; scatter fp16 to [B,H,S,DKH].
// MODE 0: wo projection; fp32 [M][N] store to out.
// ---------------------------------------------------------------------------
template <int MODE>
__global__ void __launch_bounds__(256) gemm_h(const __half* __restrict__ A,
                                              const __half* __restrict__ w0,
                                              const __half* __restrict__ w1,
                                              const __half* __restrict__ w2,
                                              void* __restrict__ d0,
                                              void* __restrict__ d1,
                                              void* __restrict__ d2) {
    extern __shared__ __align__(16) char smc[];
    float* sm = (float*)smc;

    const int tid = threadIdx.x;
    const int lane = tid & 31, wid = tid >> 5;
    const int wm = wid >> 2, wn = wid & 3;
    const int gr = lane >> 2, gc = lane & 3;
    const int n0 = blockIdx.x * 128;
    const int m0 = blockIdx.y * 128;

    const __half* W;
    void* dst;
    int rope;
    if (MODE == 1) {
        int z = blockIdx.z;
        W = z == 0 ? w0 : (z == 1 ? w1 : w2);
        dst = z == 0 ? d0 : (z == 1 ? d1 : d2);
        rope = (z < 2);
    } else {
        W = w0;
        dst = d0;
        rope = 0;
    }

    const uint32_t smb = su32(smc);

    auto fill = [&](int s, int kc) {
        uint32_t ab = smb + (uint32_t)s * GSTAGE;
        uint32_t bb = ab + GABYTES;
#pragma unroll
        for (int it = 0; it < 4; it++) {
            int idx = tid + it * 256;
            int r = idx >> 3, c = idx & 7;
            cp16(ab + (uint32_t)(r * GASTR + c * 16),
                 A + (size_t)(m0 + r) * EMBED + kc + c * 8);
        }
#pragma unroll
        for (int it = 0; it < 4; it++) {
            int idx = tid + it * 256;
            int r = idx >> 4, c = idx & 15;
            cp16(bb + (uint32_t)(r * GBSTR + c * 16),
                 W + (size_t)(kc + r) * EMBED + n0 + c * 8);
        }
        asm volatile("cp.async.commit_group;" ::: "memory");
    };

    float acc[4][4][4];
#pragma unroll
    for (int mi = 0; mi < 4; mi++)
#pragma unroll
        for (int ni = 0; ni < 4; ni++)
#pragma unroll
            for (int r = 0; r < 4; r++) acc[mi][ni][r] = 0.f;

    fill(0, 0);

    const int a_row = (lane & 15);
    const int a_kh = (lane >> 4) * 8;
    const int b_kr = ((lane >> 3) & 1) * 8 + (lane & 7);
    const int b_nh = ((lane >> 4) & 1) * 8;

    for (int i = 0; i < NCH2; i++) {
        if (i + 1 < NCH2) {
            fill((i + 1) & 1, (i + 1) * 64);
            asm volatile("cp.async.wait_group 1;" ::: "memory");
        } else {
            asm volatile("cp.async.wait_group 0;" ::: "memory");
        }
        __syncthreads();

        const uint32_t Asb = smb + (uint32_t)(i & 1) * GSTAGE;
        const uint32_t Bsb = Asb + GABYTES;

#pragma unroll
        for (int ks = 0; ks < 4; ks++) {
            const int kb = ks * 16;
            uint32_t af[4][4], bfr[2][4];
#pragma unroll
            for (int mi = 0; mi < 4; mi++)
                ldsm4(af[mi], Asb + (uint32_t)((wm * 64 + mi * 16 + a_row) * GASTR +
                                               (kb + a_kh) * 2));
#pragma unroll
            for (int p = 0; p < 2; p++)
                ldsm4t(bfr[p], Bsb + (uint32_t)((kb + b_kr) * GBSTR +
                                                (wn * 32 + p * 16 + b_nh) * 2));
#pragma unroll
            for (int mi = 0; mi < 4; mi++)
#pragma unroll
                for (int ni = 0; ni < 4; ni++)
                    mma16(acc[mi][ni], af[mi], &bfr[ni >> 1][(ni & 1) * 2]);
        }
        __syncthreads();
    }

    // ---- epilogue ----
    if (rope) {
#pragma unroll
        for (int mi = 0; mi < 4; mi++)
#pragma unroll
            for (int h2 = 0; h2 < 2; h2++) {
                int row = m0 + wm * 64 + mi * 16 + gr + h2 * 8;
                int s = row & (SEQ - 1);
#pragma unroll
                for (int ni = 0; ni < 4; ni++) {
                    int col = n0 + wn * 32 + ni * 8 + gc * 2;
                    int p = (col & 63) >> 1;
                    float2 cs = g_rope[(size_t)s * 32 + p];
                    float e = acc[mi][ni][h2 * 2 + 0];
                    float o = acc[mi][ni][h2 * 2 + 1];
                    acc[mi][ni][h2 * 2 + 0] = e * cs.x - o * cs.y;
                    acc[mi][ni][h2 * 2 + 1] = o * cs.x + e * cs.y;
                }
            }
    }

    float* stg = sm + wid * (64 * 36);
#pragma unroll
    for (int mi = 0; mi < 4; mi++)
#pragma unroll
        for (int ni = 0; ni < 4; ni++)
#pragma unroll
            for (int h2 = 0; h2 < 2; h2++) {
                int rl = mi * 16 + gr + h2 * 8;
                int cl = ni * 8 + gc * 2;
                *(float2*)&stg[rl * 36 + cl] =
                    make_float2(acc[mi][ni][h2 * 2], acc[mi][ni][h2 * 2 + 1]);
            }
    __syncwarp();

    const int lr = lane >> 3, c4 = lane & 7;
    if (MODE == 0) {
        float* df = (float*)dst;
#pragma unroll
        for (int it = 0; it < 16; it++) {
            int rl = it * 4 + lr;
            float4 v = *(float4*)&stg[rl * 36 + c4 * 4];
            int row = m0 + wm * 64 + rl;
            *(float4*)&df[(size_t)row * EMBED + n0 + wn * 32 + c4 * 4] = v;
        }
    } else {
        __half* dh = (__half*)dst;
        const int ncol = n0 + wn * 32;
        const int h = ncol >> 6, dbase = ncol & 63;
#pragma unroll
        for (int it = 0; it < 16; it++) {
            int rl = it * 4 + lr;
            float4 v = *(float4*)&stg[rl * 36 + c4 * 4];
            int row = m0 + wm * 64 + rl;
            int b = row >> 11;
            int s = row & (SEQ - 1);
            H2U8 pk;
            pk.h[0] = __floats2half2_rn(v.x, v.y);
            pk.h[1] = __floats2half2_rn(v.z, v.w);
            *(uint2*)&dh[(((size_t)(b * HEADS + h)) * SEQ + s) * DKH + dbase + c4 * 4] = pk.u;
        }
    }
}

// ---------------------------------------------------------------------------
// fp16 tensor-core flash attention, causal, no online max, register-built P
// fragments. CTA: 128 q-rows, 8 warps; 2-stage 128-row KV tiles, two 64-col
// halves per tile. Q staged through V0 buffer in the prologue (no Q region)
// -> 73728 B smem; __launch_bounds__(256,3) for 3 CTAs/SM (24 warps).
// ---------------------------------------------------------------------------
__global__ void __launch_bounds__(256, 3) flash_h(const __half* __restrict__ Q,
                                                  const __half* __restrict__ Kk,
                                                  const __half* __restrict__ V,
                                                  __half* __restrict__ Out) {
    extern __shared__ __align__(16) char fsb[];
    const int tid = threadIdx.x;
    const int lane = tid & 31, w = tid >> 5;
    const int gr = lane >> 2, gc = lane & 3;
    const int qi = gridDim.x - 1 - blockIdx.x;  // long blocks launch first
    const int bh = blockIdx.y;
    const int nt = qi + 1;  // kv tiles of 128

    const __half* Qb = Q + ((size_t)bh * SEQ + (size_t)qi * 128) * DKH;
    const __half* Kb = Kk + (size_t)bh * SEQ * DKH;
    const __half* Vb = V + (size_t)bh * SEQ * DKH;

    const uint32_t fb = su32(fsb);

    auto fillkv = [&](int buf, int j) {
        uint32_t kd = fb + (buf ? FK1B : FK0B);
        uint32_t vd = fb + (buf ? FV1B : FV0B);
        const __half* ks = Kb + (size_t)j * 128 * DKH;
        const __half* vs = Vb + (size_t)j * 128 * DKH;
#pragma unroll
        for (int it = 0; it < 4; it++) {
            int idx = tid + it * 256;
            int r = idx >> 3, c = idx & 7;
            cp16(kd + (uint32_t)(r * FST + c * 16), ks + r * 64 + c * 8);
        }
#pragma unroll
        for (int it = 0; it < 4; it++) {
            int idx = tid + it * 256;
            int r = idx >> 3, c = idx & 7;
            cp16(vd + (uint32_t)(r * FST + c * 16), vs + r * 64 + c * 8);
        }
        asm volatile("cp.async.commit_group;" ::: "memory");
    };

    // ldmatrix address components
    const int a_row = (lane & 15);
    const int a_kh = (lane >> 4) * 8;
    const int b_kr = ((lane >> 3) & 1) * 8 + (lane & 7);
    const int b_nh = ((lane >> 4) & 1) * 8;
    const int k_nr = ((lane >> 4) & 1) * 8 + (lane & 7);
    const int k_kh = ((lane >> 3) & 1) * 8;

    // ---- prologue: stage Q through the V0 buffer, grab fragments ----
    uint32_t qf[4][4];
    {
        uint32_t qd = fb + FV0B;
#pragma unroll
        for (int it = 0; it < 4; it++) {
            int idx = tid + it * 256;
            int r = idx >> 3, c = idx & 7;
            cp16(qd + (uint32_t)(r * FST + c * 16), Qb + r * 64 + c * 8);
        }
        asm volatile("cp.async.commit_group;" ::: "memory");
        asm volatile("cp.async.wait_group 0;" ::: "memory");
        __syncthreads();
#pragma unroll
        for (int ks = 0; ks < 4; ks++)
            ldsm4(qf[ks], qd + (uint32_t)((w * 16 + a_row) * FST + (ks * 16 + a_kh) * 2));
        __syncthreads();  // V0 buffer free for the KV pipeline
    }

    fillkv(0, 0);
    if (nt > 1) fillkv(1, 1);

    float liA = 0.f, liB = 0.f;
    float oacc[8][4];
#pragma unroll
    for (int n8 = 0; n8 < 8; n8++)
#pragma unroll
        for (int r = 0; r < 4; r++) oacc[n8][r] = 0.f;

    const int wrow = qi * 128 + w * 16;

    for (int j = 0; j < nt; j++) {
        if (j <= nt - 2)
            asm volatile("cp.async.wait_group 1;" ::: "memory");
        else
            asm volatile("cp.async.wait_group 0;" ::: "memory");
        __syncthreads();

        const uint32_t Ksb = fb + ((j & 1) ? FK1B : FK0B);
        const uint32_t Vsb = fb + ((j & 1) ? FV1B : FV0B);

#pragma unroll
        for (int half = 0; half < 2; half++) {
            const int colbase = j * 128 + half * 64;
            if (colbase > wrow + 15) break;  // rest of tile fully masked

            const uint32_t Kh = Ksb + (uint32_t)(half * 64 * FST);
            const uint32_t Vh = Vsb + (uint32_t)(half * 64 * FST);
            const bool diag = (colbase + 63 > wrow);

            // P fragments built in registers: pf[pg] covers S cols pg*16..+15
            uint32_t pf[4][4];

#pragma unroll
            for (int pg = 0; pg < 4; pg++) {
                if (diag && colbase + pg * 16 > wrow + 15) {
                    pf[pg][0] = pf[pg][1] = pf[pg][2] = pf[pg][3] = 0u;
                    continue;
                }
                float s0[4] = {0.f, 0.f, 0.f, 0.f};
                float s1[4] = {0.f, 0.f, 0.f, 0.f};
#pragma unroll
                for (int ks = 0; ks < 4; ks++) {
                    uint32_t kf[4];
                    ldsm4(kf, Kh + (uint32_t)((pg * 16 + k_nr) * FST + (ks * 16 + k_kh) * 2));
                    mma16(s0, qf[ks], &kf[0]);
                    mma16(s1, qf[ks], &kf[2]);
                }
                float p00, p01, p02, p03, p10, p11, p12, p13;
                if (diag) {
                    int r0 = wrow + gr;
                    int c0 = colbase + pg * 16 + 2 * gc;
                    int c1 = c0 + 8;
                    p00 = (c0 > r0) ? 0.f : __expf(s0[0] * 0.125f);
                    p01 = (c0 + 1 > r0) ? 0.f : __expf(s0[1] * 0.125f);
                    p02 = (c0 > r0 + 8) ? 0.f : __expf(s0[2] * 0.125f);
                    p03 = (c0 + 1 > r0 + 8) ? 0.f : __expf(s0[3] * 0.125f);
                    p10 = (c1 > r0) ? 0.f : __expf(s1[0] * 0.125f);
                    p11 = (c1 + 1 > r0) ? 0.f : __expf(s1[1] * 0.125f);
                    p12 = (c1 > r0 + 8) ? 0.f : __expf(s1[2] * 0.125f);
                    p13 = (c1 + 1 > r0 + 8) ? 0.f : __expf(s1[3] * 0.125f);
                } else {
                    p00 = __expf(s0[0] * 0.125f);
                    p01 = __expf(s0[1] * 0.125f);
                    p02 = __expf(s0[2] * 0.125f);
                    p03 = __expf(s0[3] * 0.125f);
                    p10 = __expf(s1[0] * 0.125f);
                    p11 = __expf(s1[1] * 0.125f);
                    p12 = __expf(s1[2] * 0.125f);
                    p13 = __expf(s1[3] * 0.125f);
                }
                liA += p00 + p01 + p10 + p11;
                liB += p02 + p03 + p12 + p13;
                pf[pg][0] = packh2(p00, p01);
                pf[pg][1] = packh2(p02, p03);
                pf[pg][2] = packh2(p10, p11);
                pf[pg][3] = packh2(p12, p13);
            }

            // O += P V (pf[kc] is the A-frag for P's k-chunk kc)
#pragma unroll
            for (int kc = 0; kc < 4; kc++) {
                if (diag && colbase + kc * 16 > wrow + 15) continue;  // pf zero
                const int kb = kc * 16;
#pragma unroll
                for (int p = 0; p < 4; p++) {
                    uint32_t vf[4];
                    ldsm4t(vf, Vh + (uint32_t)((kb + b_kr) * FST + (p * 16 + b_nh) * 2));
                    mma16(oacc[2 * p], pf[kc], &vf[0]);
                    mma16(oacc[2 * p + 1], pf[kc], &vf[2]);
                }
            }
        }

        __syncthreads();  // all warps done with this KV buffer
        if (j + 2 < nt) fillkv(j & 1, j + 2);
    }

    // final row-sum reduction + normalize + write [B,S,E]
    liA += __shfl_xor_sync(0xffffffffu, liA, 1);
    liA += __shfl_xor_sync(0xffffffffu, liA, 2);
    liB += __shfl_xor_sync(0xffffffffu, liB, 1);
    liB += __shfl_xor_sync(0xffffffffu, liB, 2);

    const int b = bh >> 4, h = bh & 15;
    const int row = wrow + gr;
    float invA = 1.f / liA, invB = 1.f / liB;
    __half* o0 = Out + ((size_t)b * SEQ + row) * EMBED + h * 64;
    __half* o1 = Out + ((size_t)b * SEQ + row + 8) * EMBED + h * 64;
#pragma unroll
    for (int n8 = 0; n8 < 8; n8++) {
        *(__half2*)&o0[n8 * 8 + 2 * gc] =
            __floats2half2_rn(oacc[n8][0] * invA, oacc[n8][1] * invA);
        *(__half2*)&o1[n8 * 8 + 2 * gc] =
            __floats2half2_rn(oacc[n8][2] * invB, oacc[n8][3] * invB);
    }
}

extern "C" void kernel_launch(void* const* d_in, const int* in_sizes, int n_in,
                              void* d_out, int out_size) {
    (void)in_sizes;
    (void)n_in;
    (void)out_size;
    const float* x = (const float*)d_in[0];
    const float* wq = (const float*)d_in[1];
    const float* wk = (const float*)d_in[2];
    const float* wv = (const float*)d_in[3];
    const float* wo = (const float*)d_in[4];
    float* out = (float*)d_out;

    __half *x16, *w16, *q, *k, *v, *attn;
    cudaGetSymbolAddress((void**)&x16, g_x16);
    cudaGetSymbolAddress((void**)&w16, g_w16);
    cudaGetSymbolAddress((void**)&q, g_q);
    cudaGetSymbolAddress((void**)&k, g_k);
    cudaGetSymbolAddress((void**)&v, g_v);
    cudaGetSymbolAddress((void**)&attn, g_attn);

    cudaFuncSetAttribute(gemm_h<1>, cudaFuncAttributeMaxDynamicSharedMemorySize, GSMEM);
    cudaFuncSetAttribute(gemm_h<0>, cudaFuncAttributeMaxDynamicSharedMemorySize, GSMEM);
    cudaFuncSetAttribute(flash_h, cudaFuncAttributeMaxDynamicSharedMemorySize, FSMEMB);

    rope_table_kernel<<<SEQ * 32 / 256, 256>>>();
    cvt_fp16<<<(MTOT * EMBED / 4 + WSZ) / 256, 256>>>(x, wq, wk, wv, wo);
    gemm_h<1><<<dim3(EMBED / 128, MTOT / 128, 3), 256, GSMEM>>>(
        x16, w16, w16 + WSZ, w16 + 2 * WSZ, q, k, v);
    flash_h<<<dim3(SEQ / 128, BATCH * HEADS), 256, FSMEMB>>>(q, k, v, attn);
    gemm_h<0><<<dim3(EMBED / 128, MTOT / 128, 1), 256, GSMEM>>>(
        attn, w16 + 3 * WSZ, nullptr, nullptr, out, nullptr, nullptr);
}

// round 14
// speedup vs baseline: 1.0323x; 1.0207x over previous
#include <cuda_runtime.h>
#include <cuda_fp16.h>
#include <math.h>
#include <stdint.h>

#define EMBED 1024
#define HEADS 16
#define DKH 64
#define BATCH 2
#define SEQ 2048
#define MTOT (BATCH * SEQ)   // 4096
#define WSZ (EMBED * EMBED)  // 1048576

// ---- fp16 GEMM tiling: CTA 128x128, BK=64, 8 warps (2x4), warp tile 64x32 ----
#define NCH2 16            // 1024/64 k-chunks
#define GASTR 144          // A smem row stride BYTES (72 halves)
#define GBSTR 272          // B smem row stride BYTES (136 halves)
#define GABYTES (128 * GASTR)       // 18432
#define GBBYTES (64 * GBSTR)        // 17408
#define GSTAGE (GABYTES + GBBYTES)  // 35840
#define GSMEM 73728                 // max(2*GSTAGE=71680, epilogue 8*64*36*4)

// ---- flash fp16 smem (bytes): KV tiles 128x64 halves, stride 144B, 2 stages
//      + dedicated Q region (R12-measured layout) ----
#define FST 144
#define FK0B 0
#define FK1B 18432
#define FV0B 36864
#define FV1B 55296
#define FQPB 73728
#define FSMEMB (FQPB + 128 * FST)  // 92160

// Scratch (allocation-free rule: __device__ globals)
__device__ __half g_x16[(size_t)MTOT * EMBED];
__device__ __half g_w16[(size_t)4 * WSZ];
__device__ __half g_q[(size_t)BATCH * HEADS * SEQ * DKH];
__device__ __half g_k[(size_t)BATCH * HEADS * SEQ * DKH];
__device__ __half g_v[(size_t)BATCH * HEADS * SEQ * DKH];
__device__ __half g_attn[(size_t)MTOT * EMBED];
__device__ float2 g_rope[(size_t)SEQ * 32];

// ---------------------------------------------------------------------------
// helpers
// ---------------------------------------------------------------------------
__device__ __forceinline__ uint32_t su32(const void* p) {
    uint32_t a;
    asm("{ .reg .u64 t; cvta.to.shared.u64 t, %1; cvt.u32.u64 %0, t; }"
        : "=r"(a) : "l"(p));
    return a;
}

__device__ __forceinline__ void cp16(uint32_t dst, const void* src) {
    asm volatile("cp.async.cg.shared.global [%0], [%1], 16;" :: "r"(dst), "l"(src));
}

__device__ __forceinline__ void ldsm4(uint32_t* r, uint32_t a) {
    asm volatile("ldmatrix.sync.aligned.m8n8.x4.shared.b16 {%0,%1,%2,%3}, [%4];"
                 : "=r"(r[0]), "=r"(r[1]), "=r"(r[2]), "=r"(r[3]) : "r"(a));
}

__device__ __forceinline__ void ldsm4t(uint32_t* r, uint32_t a) {
    asm volatile("ldmatrix.sync.aligned.m8n8.x4.trans.shared.b16 {%0,%1,%2,%3}, [%4];"
                 : "=r"(r[0]), "=r"(r[1]), "=r"(r[2]), "=r"(r[3]) : "r"(a));
}

__device__ __forceinline__ void mma16(float* d, const uint32_t* a, const uint32_t* b) {
    asm volatile(
        "mma.sync.aligned.m16n8k16.row.col.f32.f16.f16.f32 "
        "{%0,%1,%2,%3}, {%4,%5,%6,%7}, {%8,%9}, {%0,%1,%2,%3};"
        : "+f"(d[0]), "+f"(d[1]), "+f"(d[2]), "+f"(d[3])
        : "r"(a[0]), "r"(a[1]), "r"(a[2]), "r"(a[3]), "r"(b[0]), "r"(b[1]));
}

__device__ __forceinline__ uint32_t packh2(float lo, float hi) {
    __half2 h = __floats2half2_rn(lo, hi);
    return *(uint32_t*)&h;
}

union H2U8 {
    __half2 h[2];
    uint2 u;
};

// ---------------------------------------------------------------------------
// prep: RoPE table + fused fp32->fp16 conversion (R11-validated form)
// ---------------------------------------------------------------------------
__global__ void rope_table_kernel() {
    int idx = blockIdx.x * 256 + threadIdx.x;
    int s = idx >> 5, p = idx & 31;
    double inv = 1.0 / pow(10000.0, (double)(2 * p) / 64.0);
    float ang = (float)s * (float)inv;
    g_rope[idx] = make_float2(cosf(ang), sinf(ang));
}

__global__ void __launch_bounds__(256) cvt_fp16(const float* __restrict__ x,
                                                const float* __restrict__ wq,
                                                const float* __restrict__ wk,
                                                const float* __restrict__ wv,
                                                const float* __restrict__ wo) {
    const int XN4 = MTOT * EMBED / 4;
    int i4 = blockIdx.x * 256 + threadIdx.x;
    const float* src;
    __half* dst;
    size_t off;
    if (i4 < XN4) {
        src = x;
        dst = g_x16;
        off = (size_t)i4 * 4;
    } else {
        int r = i4 - XN4;
        int wsel = r >> 18;  // WSZ/4 = 2^18
        int o4 = r & ((1 << 18) - 1);
        src = wsel == 0 ? wq : (wsel == 1 ? wk : (wsel == 2 ? wv : wo));
        dst = g_w16 + (size_t)wsel * WSZ;
        off = (size_t)o4 * 4;
    }
    float4 v = *(const float4*)(src + off);
    H2U8 pk;
    pk.h[0] = __floats2half2_rn(v.x, v.y);
    pk.h[1] = __floats2half2_rn(v.z, v.w);
    *(uint2*)(dst + off) = pk.u;
}

// ---------------------------------------------------------------------------
// fp16 GEMM: C[4096,1024] = A @ W (both fp16, W row-major [K][N]).
// CTA 128x128, BK=64, 2-stage cp.async, ldmatrix fragments, fp32 accum.
// MODE 1: z selects wq/wk/wv; RoPE for z<2; scatter fp16 to [B,H,S,DKH].
// MODE 0: wo projection; fp32 [M][N] store to out.
// ---------------------------------------------------------------------------
template <int MODE>
__global__ void __launch_bounds__(256) gemm_h(const __half* __restrict__ A,
                                              const __half* __restrict__ w0,
                                              const __half* __restrict__ w1,
                                              const __half* __restrict__ w2,
                                              void* __restrict__ d0,
                                              void* __restrict__ d1,
                                              void* __restrict__ d2) {
    extern __shared__ __align__(16) char smc[];
    float* sm = (float*)smc;

    const int tid = threadIdx.x;
    const int lane = tid & 31, wid = tid >> 5;
    const int wm = wid >> 2, wn = wid & 3;
    const int gr = lane >> 2, gc = lane & 3;
    const int n0 = blockIdx.x * 128;
    const int m0 = blockIdx.y * 128;

    const __half* W;
    void* dst;
    int rope;
    if (MODE == 1) {
        int z = blockIdx.z;
        W = z == 0 ? w0 : (z == 1 ? w1 : w2);
        dst = z == 0 ? d0 : (z == 1 ? d1 : d2);
        rope = (z < 2);
    } else {
        W = w0;
        dst = d0;
        rope = 0;
    }

    const uint32_t smb = su32(smc);

    auto fill = [&](int s, int kc) {
        uint32_t ab = smb + (uint32_t)s * GSTAGE;
        uint32_t bb = ab + GABYTES;
#pragma unroll
        for (int it = 0; it < 4; it++) {
            int idx = tid + it * 256;
            int r = idx >> 3, c = idx & 7;
            cp16(ab + (uint32_t)(r * GASTR + c * 16),
                 A + (size_t)(m0 + r) * EMBED + kc + c * 8);
        }
#pragma unroll
        for (int it = 0; it < 4; it++) {
            int idx = tid + it * 256;
            int r = idx >> 4, c = idx & 15;
            cp16(bb + (uint32_t)(r * GBSTR + c * 16),
                 W + (size_t)(kc + r) * EMBED + n0 + c * 8);
        }
        asm volatile("cp.async.commit_group;" ::: "memory");
    };

    float acc[4][4][4];
#pragma unroll
    for (int mi = 0; mi < 4; mi++)
#pragma unroll
        for (int ni = 0; ni < 4; ni++)
#pragma unroll
            for (int r = 0; r < 4; r++) acc[mi][ni][r] = 0.f;

    fill(0, 0);

    const int a_row = (lane & 15);
    const int a_kh = (lane >> 4) * 8;
    const int b_kr = ((lane >> 3) & 1) * 8 + (lane & 7);
    const int b_nh = ((lane >> 4) & 1) * 8;

    for (int i = 0; i < NCH2; i++) {
        if (i + 1 < NCH2) {
            fill((i + 1) & 1, (i + 1) * 64);
            asm volatile("cp.async.wait_group 1;" ::: "memory");
        } else {
            asm volatile("cp.async.wait_group 0;" ::: "memory");
        }
        __syncthreads();

        const uint32_t Asb = smb + (uint32_t)(i & 1) * GSTAGE;
        const uint32_t Bsb = Asb + GABYTES;

#pragma unroll
        for (int ks = 0; ks < 4; ks++) {
            const int kb = ks * 16;
            uint32_t af[4][4], bfr[2][4];
#pragma unroll
            for (int mi = 0; mi < 4; mi++)
                ldsm4(af[mi], Asb + (uint32_t)((wm * 64 + mi * 16 + a_row) * GASTR +
                                               (kb + a_kh) * 2));
#pragma unroll
            for (int p = 0; p < 2; p++)
                ldsm4t(bfr[p], Bsb + (uint32_t)((kb + b_kr) * GBSTR +
                                                (wn * 32 + p * 16 + b_nh) * 2));
#pragma unroll
            for (int mi = 0; mi < 4; mi++)
#pragma unroll
                for (int ni = 0; ni < 4; ni++)
                    mma16(acc[mi][ni], af[mi], &bfr[ni >> 1][(ni & 1) * 2]);
        }
        __syncthreads();
    }

    // ---- epilogue ----
    if (rope) {
#pragma unroll
        for (int mi = 0; mi < 4; mi++)
#pragma unroll
            for (int h2 = 0; h2 < 2; h2++) {
                int row = m0 + wm * 64 + mi * 16 + gr + h2 * 8;
                int s = row & (SEQ - 1);
#pragma unroll
                for (int ni = 0; ni < 4; ni++) {
                    int col = n0 + wn * 32 + ni * 8 + gc * 2;
                    int p = (col & 63) >> 1;
                    float2 cs = g_rope[(size_t)s * 32 + p];
                    float e = acc[mi][ni][h2 * 2 + 0];
                    float o = acc[mi][ni][h2 * 2 + 1];
                    acc[mi][ni][h2 * 2 + 0] = e * cs.x - o * cs.y;
                    acc[mi][ni][h2 * 2 + 1] = o * cs.x + e * cs.y;
                }
            }
    }

    float* stg = sm + wid * (64 * 36);
#pragma unroll
    for (int mi = 0; mi < 4; mi++)
#pragma unroll
        for (int ni = 0; ni < 4; ni++)
#pragma unroll
            for (int h2 = 0; h2 < 2; h2++) {
                int rl = mi * 16 + gr + h2 * 8;
                int cl = ni * 8 + gc * 2;
                *(float2*)&stg[rl * 36 + cl] =
                    make_float2(acc[mi][ni][h2 * 2], acc[mi][ni][h2 * 2 + 1]);
            }
    __syncwarp();

    const int lr = lane >> 3, c4 = lane & 7;
    if (MODE == 0) {
        float* df = (float*)dst;
#pragma unroll
        for (int it = 0; it < 16; it++) {
            int rl = it * 4 + lr;
            float4 v = *(float4*)&stg[rl * 36 + c4 * 4];
            int row = m0 + wm * 64 + rl;
            *(float4*)&df[(size_t)row * EMBED + n0 + wn * 32 + c4 * 4] = v;
        }
    } else {
        __half* dh = (__half*)dst;
        const int ncol = n0 + wn * 32;
        const int h = ncol >> 6, dbase = ncol & 63;
#pragma unroll
        for (int it = 0; it < 16; it++) {
            int rl = it * 4 + lr;
            float4 v = *(float4*)&stg[rl * 36 + c4 * 4];
            int row = m0 + wm * 64 + rl;
            int b = row >> 11;
            int s = row & (SEQ - 1);
            H2U8 pk;
            pk.h[0] = __floats2half2_rn(v.x, v.y);
            pk.h[1] = __floats2half2_rn(v.z, v.w);
            *(uint2*)&dh[(((size_t)(b * HEADS + h)) * SEQ + s) * DKH + dbase + c4 * 4] = pk.u;
        }
    }
}

// ---------------------------------------------------------------------------
// fp16 tensor-core flash attention, causal, no online max, register-built P.
// Merged per-column-group loop: QK(pg) -> exp -> PV(pg), so QK(pg+1) can
// overlap PV(pg)'s serial accumulator chains. oacc accumulation order across
// pg is identical to R12 -> bit-identical output.
// CTA: 128 q-rows, 8 warps; 2-stage 128-row KV tiles, two 64-col halves.
// ---------------------------------------------------------------------------
__global__ void __launch_bounds__(256) flash_h(const __half* __restrict__ Q,
                                               const __half* __restrict__ Kk,
                                               const __half* __restrict__ V,
                                               __half* __restrict__ Out) {
    extern __shared__ __align__(16) char fsb[];
    const int tid = threadIdx.x;
    const int lane = tid & 31, w = tid >> 5;
    const int gr = lane >> 2, gc = lane & 3;
    const int qi = gridDim.x - 1 - blockIdx.x;  // long blocks launch first
    const int bh = blockIdx.y;
    const int nt = qi + 1;  // kv tiles of 128

    const __half* Qb = Q + ((size_t)bh * SEQ + (size_t)qi * 128) * DKH;
    const __half* Kb = Kk + (size_t)bh * SEQ * DKH;
    const __half* Vb = V + (size_t)bh * SEQ * DKH;

    const uint32_t fb = su32(fsb);

    auto fillkv = [&](int buf, int j) {
        uint32_t kd = fb + (buf ? FK1B : FK0B);
        uint32_t vd = fb + (buf ? FV1B : FV0B);
        const __half* ks = Kb + (size_t)j * 128 * DKH;
        const __half* vs = Vb + (size_t)j * 128 * DKH;
#pragma unroll
        for (int it = 0; it < 4; it++) {
            int idx = tid + it * 256;
            int r = idx >> 3, c = idx & 7;
            cp16(kd + (uint32_t)(r * FST + c * 16), ks + r * 64 + c * 8);
        }
#pragma unroll
        for (int it = 0; it < 4; it++) {
            int idx = tid + it * 256;
            int r = idx >> 3, c = idx & 7;
            cp16(vd + (uint32_t)(r * FST + c * 16), vs + r * 64 + c * 8);
        }
        asm volatile("cp.async.commit_group;" ::: "memory");
    };

    {  // Q tile (128x64)
        uint32_t qd = fb + FQPB;
#pragma unroll
        for (int it = 0; it < 4; it++) {
            int idx = tid + it * 256;
            int r = idx >> 3, c = idx & 7;
            cp16(qd + (uint32_t)(r * FST + c * 16), Qb + r * 64 + c * 8);
        }
    }
    fillkv(0, 0);
    if (nt > 1) fillkv(1, 1);

    if (nt > 1)
        asm volatile("cp.async.wait_group 1;" ::: "memory");
    else
        asm volatile("cp.async.wait_group 0;" ::: "memory");
    __syncthreads();

    // ldmatrix address components
    const int a_row = (lane & 15);
    const int a_kh = (lane >> 4) * 8;
    const int b_kr = ((lane >> 3) & 1) * 8 + (lane & 7);
    const int b_nh = ((lane >> 4) & 1) * 8;
    const int k_nr = ((lane >> 4) & 1) * 8 + (lane & 7);
    const int k_kh = ((lane >> 3) & 1) * 8;

    // Q fragments persist in registers
    uint32_t qf[4][4];
#pragma unroll
    for (int ks = 0; ks < 4; ks++)
        ldsm4(qf[ks], fb + FQPB + (uint32_t)((w * 16 + a_row) * FST + (ks * 16 + a_kh) * 2));

    float liA = 0.f, liB = 0.f;
    float oacc[8][4];
#pragma unroll
    for (int n8 = 0; n8 < 8; n8++)
#pragma unroll
        for (int r = 0; r < 4; r++) oacc[n8][r] = 0.f;

    const int wrow = qi * 128 + w * 16;

    for (int j = 0; j < nt; j++) {
        if (j <= nt - 2)
            asm volatile("cp.async.wait_group 1;" ::: "memory");
        else
            asm volatile("cp.async.wait_group 0;" ::: "memory");
        __syncthreads();

        const uint32_t Ksb = fb + ((j & 1) ? FK1B : FK0B);
        const uint32_t Vsb = fb + ((j & 1) ? FV1B : FV0B);

#pragma unroll
        for (int half = 0; half < 2; half++) {
            const int colbase = j * 128 + half * 64;
            if (colbase > wrow + 15) break;  // rest of tile fully masked

            const uint32_t Kh = Ksb + (uint32_t)(half * 64 * FST);
            const uint32_t Vh = Vsb + (uint32_t)(half * 64 * FST);
            const bool diag = (colbase + 63 > wrow);

#pragma unroll
            for (int pg = 0; pg < 4; pg++) {
                if (diag && colbase + pg * 16 > wrow + 15) continue;  // masked group

                // ---- QK for this column group ----
                float s0[4] = {0.f, 0.f, 0.f, 0.f};
                float s1[4] = {0.f, 0.f, 0.f, 0.f};
#pragma unroll
                for (int ks = 0; ks < 4; ks++) {
                    uint32_t kf[4];
                    ldsm4(kf, Kh + (uint32_t)((pg * 16 + k_nr) * FST + (ks * 16 + k_kh) * 2));
                    mma16(s0, qf[ks], &kf[0]);
                    mma16(s1, qf[ks], &kf[2]);
                }

                // ---- exp + mask + pack to A-fragment ----
                float p00, p01, p02, p03, p10, p11, p12, p13;
                if (diag) {
                    int r0 = wrow + gr;
                    int c0 = colbase + pg * 16 + 2 * gc;
                    int c1 = c0 + 8;
                    p00 = (c0 > r0) ? 0.f : __expf(s0[0] * 0.125f);
                    p01 = (c0 + 1 > r0) ? 0.f : __expf(s0[1] * 0.125f);
                    p02 = (c0 > r0 + 8) ? 0.f : __expf(s0[2] * 0.125f);
                    p03 = (c0 + 1 > r0 + 8) ? 0.f : __expf(s0[3] * 0.125f);
                    p10 = (c1 > r0) ? 0.f : __expf(s1[0] * 0.125f);
                    p11 = (c1 + 1 > r0) ? 0.f : __expf(s1[1] * 0.125f);
                    p12 = (c1 > r0 + 8) ? 0.f : __expf(s1[2] * 0.125f);
                    p13 = (c1 + 1 > r0 + 8) ? 0.f : __expf(s1[3] * 0.125f);
                } else {
                    p00 = __expf(s0[0] * 0.125f);
                    p01 = __expf(s0[1] * 0.125f);
                    p02 = __expf(s0[2] * 0.125f);
                    p03 = __expf(s0[3] * 0.125f);
                    p10 = __expf(s1[0] * 0.125f);
                    p11 = __expf(s1[1] * 0.125f);
                    p12 = __expf(s1[2] * 0.125f);
                    p13 = __expf(s1[3] * 0.125f);
                }
                liA += p00 + p01 + p10 + p11;
                liB += p02 + p03 + p12 + p13;
                uint32_t pf[4];
                pf[0] = packh2(p00, p01);
                pf[1] = packh2(p02, p03);
                pf[2] = packh2(p10, p11);
                pf[3] = packh2(p12, p13);

                // ---- PV for this column group (k-chunk = pg) ----
                const int kb = pg * 16;
#pragma unroll
                for (int p = 0; p < 4; p++) {
                    uint32_t vf[4];
                    ldsm4t(vf, Vh + (uint32_t)((kb + b_kr) * FST + (p * 16 + b_nh) * 2));
                    mma16(oacc[2 * p], pf, &vf[0]);
                    mma16(oacc[2 * p + 1], pf, &vf[2]);
                }
            }
        }

        __syncthreads();  // all warps done with this KV buffer
        if (j + 2 < nt) fillkv(j & 1, j + 2);
    }

    // final row-sum reduction + normalize + write [B,S,E]
    liA += __shfl_xor_sync(0xffffffffu, liA, 1);
    liA += __shfl_xor_sync(0xffffffffu, liA, 2);
    liB += __shfl_xor_sync(0xffffffffu, liB, 1);
    liB += __shfl_xor_sync(0xffffffffu, liB, 2);

    const int b = bh >> 4, h = bh & 15;
    const int row = wrow + gr;
    float invA = 1.f / liA, invB = 1.f / liB;
    __half* o0 = Out + ((size_t)b * SEQ + row) * EMBED + h * 64;
    __half* o1 = Out + ((size_t)b * SEQ + row + 8) * EMBED + h * 64;
#pragma unroll
    for (int n8 = 0; n8 < 8; n8++) {
        *(__half2*)&o0[n8 * 8 + 2 * gc] =
            __floats2half2_rn(oacc[n8][0] * invA, oacc[n8][1] * invA);
        *(__half2*)&o1[n8 * 8 + 2 * gc] =
            __floats2half2_rn(oacc[n8][2] * invB, oacc[n8][3] * invB);
    }
}

extern "C" void kernel_launch(void* const* d_in, const int* in_sizes, int n_in,
                              void* d_out, int out_size) {
    (void)in_sizes;
    (void)n_in;
    (void)out_size;
    const float* x = (const float*)d_in[0];
    const float* wq = (const float*)d_in[1];
    const float* wk = (const float*)d_in[2];
    const float* wv = (const float*)d_in[3];
    const float* wo = (const float*)d_in[4];
    float* out = (float*)d_out;

    __half *x16, *w16, *q, *k, *v, *attn;
    cudaGetSymbolAddress((void**)&x16, g_x16);
    cudaGetSymbolAddress((void**)&w16, g_w16);
    cudaGetSymbolAddress((void**)&q, g_q);
    cudaGetSymbolAddress((void**)&k, g_k);
    cudaGetSymbolAddress((void**)&v, g_v);
    cudaGetSymbolAddress((void**)&attn, g_attn);

    cudaFuncSetAttribute(gemm_h<1>, cudaFuncAttributeMaxDynamicSharedMemorySize, GSMEM);
    cudaFuncSetAttribute(gemm_h<0>, cudaFuncAttributeMaxDynamicSharedMemorySize, GSMEM);
    cudaFuncSetAttribute(flash_h, cudaFuncAttributeMaxDynamicSharedMemorySize, FSMEMB);

    rope_table_kernel<<<SEQ * 32 / 256, 256>>>();
    cvt_fp16<<<(MTOT * EMBED / 4 + WSZ) / 256, 256>>>(x, wq, wk, wv, wo);
    gemm_h<1><<<dim3(EMBED / 128, MTOT / 128, 3), 256, GSMEM>>>(
        x16, w16, w16 + WSZ, w16 + 2 * WSZ, q, k, v);
    flash_h<<<dim3(SEQ / 128, BATCH * HEADS), 256, FSMEMB>>>(q, k, v, attn);
    gemm_h<0><<<dim3(EMBED / 128, MTOT / 128, 1), 256, GSMEM>>>(
        attn, w16 + 3 * WSZ, nullptr, nullptr, out, nullptr, nullptr);
}

// round 15
// speedup vs baseline: 1.0525x; 1.0196x over previous
#include <cuda_runtime.h>
#include <cuda_fp16.h>
#include <math.h>
#include <stdint.h>

#define EMBED 1024
#define HEADS 16
#define DKH 64
#define BATCH 2
#define SEQ 2048
#define MTOT (BATCH * SEQ)   // 4096
#define WSZ (EMBED * EMBED)  // 1048576

// ---- fp16 GEMM tiling: CTA 128x128, BK=64, 8 warps (2x4), warp tile 64x32 ----
#define NCH2 16            // 1024/64 k-chunks
#define GASTR 144          // A smem row stride BYTES (72 halves)
#define GBSTR 272          // B smem row stride BYTES (136 halves)
#define GABYTES (128 * GASTR)       // 18432
#define GBBYTES (64 * GBSTR)        // 17408
#define GSTAGE (GABYTES + GBBYTES)  // 35840
#define GSMEM 73728                 // max(2*GSTAGE=71680, epilogue 8*64*36*4)

// ---- flash fp16 smem (bytes): 2-stage KV tiles 128x64 halves, stride 144B.
//      Q staged through V0 in the prologue; no dedicated Q region.
//      73728 B -> 3 CTAs/SM; merged-loop body is 80 regs <= 84-reg budget. ----
#define FST 144
#define FK0B 0
#define FK1B 18432
#define FV0B 36864
#define FV1B 55296
#define FSMEMB 73728

// Scratch (allocation-free rule: __device__ globals)
__device__ __half g_x16[(size_t)MTOT * EMBED];
__device__ __half g_w16[(size_t)4 * WSZ];
__device__ __half g_q[(size_t)BATCH * HEADS * SEQ * DKH];
__device__ __half g_k[(size_t)BATCH * HEADS * SEQ * DKH];
__device__ __half g_v[(size_t)BATCH * HEADS * SEQ * DKH];
__device__ __half g_attn[(size_t)MTOT * EMBED];
__device__ float2 g_rope[(size_t)SEQ * 32];

// ---------------------------------------------------------------------------
// helpers
// ---------------------------------------------------------------------------
__device__ __forceinline__ uint32_t su32(const void* p) {
    uint32_t a;
    asm("{ .reg .u64 t; cvta.to.shared.u64 t, %1; cvt.u32.u64 %0, t; }"
        : "=r"(a) : "l"(p));
    return a;
}

__device__ __forceinline__ void cp16(uint32_t dst, const void* src) {
    asm volatile("cp.async.cg.shared.global [%0], [%1], 16;" :: "r"(dst), "l"(src));
}

__device__ __forceinline__ void ldsm4(uint32_t* r, uint32_t a) {
    asm volatile("ldmatrix.sync.aligned.m8n8.x4.shared.b16 {%0,%1,%2,%3}, [%4];"
                 : "=r"(r[0]), "=r"(r[1]), "=r"(r[2]), "=r"(r[3]) : "r"(a));
}

__device__ __forceinline__ void ldsm4t(uint32_t* r, uint32_t a) {
    asm volatile("ldmatrix.sync.aligned.m8n8.x4.trans.shared.b16 {%0,%1,%2,%3}, [%4];"
                 : "=r"(r[0]), "=r"(r[1]), "=r"(r[2]), "=r"(r[3]) : "r"(a));
}

__device__ __forceinline__ void mma16(float* d, const uint32_t* a, const uint32_t* b) {
    asm volatile(
        "mma.sync.aligned.m16n8k16.row.col.f32.f16.f16.f32 "
        "{%0,%1,%2,%3}, {%4,%5,%6,%7}, {%8,%9}, {%0,%1,%2,%3};"
        : "+f"(d[0]), "+f"(d[1]), "+f"(d[2]), "+f"(d[3])
        : "r"(a[0]), "r"(a[1]), "r"(a[2]), "r"(a[3]), "r"(b[0]), "r"(b[1]));
}

__device__ __forceinline__ uint32_t packh2(float lo, float hi) {
    __half2 h = __floats2half2_rn(lo, hi);
    return *(uint32_t*)&h;
}

union H2U8 {
    __half2 h[2];
    uint2 u;
};

// ---------------------------------------------------------------------------
// prep: RoPE table + fused fp32->fp16 conversion (R11-validated form)
// ---------------------------------------------------------------------------
__global__ void rope_table_kernel() {
    int idx = blockIdx.x * 256 + threadIdx.x;
    int s = idx >> 5, p = idx & 31;
    double inv = 1.0 / pow(10000.0, (double)(2 * p) / 64.0);
    float ang = (float)s * (float)inv;
    g_rope[idx] = make_float2(cosf(ang), sinf(ang));
}

__global__ void __launch_bounds__(256) cvt_fp16(const float* __restrict__ x,
                                                const float* __restrict__ wq,
                                                const float* __restrict__ wk,
                                                const float* __restrict__ wv,
                                                const float* __restrict__ wo) {
    const int XN4 = MTOT * EMBED / 4;
    int i4 = blockIdx.x * 256 + threadIdx.x;
    const float* src;
    __half* dst;
    size_t off;
    if (i4 < XN4) {
        src = x;
        dst = g_x16;
        off = (size_t)i4 * 4;
    } else {
        int r = i4 - XN4;
        int wsel = r >> 18;  // WSZ/4 = 2^18
        int o4 = r & ((1 << 18) - 1);
        src = wsel == 0 ? wq : (wsel == 1 ? wk : (wsel == 2 ? wv : wo));
        dst = g_w16 + (size_t)wsel * WSZ;
        off = (size_t)o4 * 4;
    }
    float4 v = *(const float4*)(src + off);
    H2U8 pk;
    pk.h[0] = __floats2half2_rn(v.x, v.y);
    pk.h[1] = __floats2half2_rn(v.z, v.w);
    *(uint2*)(dst + off) = pk.u;
}

// ---------------------------------------------------------------------------
// fp16 GEMM: C[4096,1024] = A @ W (both fp16, W row-major [K][N]).
// CTA 128x128, BK=64, 2-stage cp.async, ldmatrix fragments, fp32 accum.
// MODE 1: z selects wq/wk/wv; RoPE for z<2; scatter fp16 to [B,H,S,DKH].
// MODE 0: wo projection; fp32 [M][N] store to out.
// ---------------------------------------------------------------------------
template <int MODE>
__global__ void __launch_bounds__(256) gemm_h(const __half* __restrict__ A,
                                              const __half* __restrict__ w0,
                                              const __half* __restrict__ w1,
                                              const __half* __restrict__ w2,
                                              void* __restrict__ d0,
                                              void* __restrict__ d1,
                                              void* __restrict__ d2) {
    extern __shared__ __align__(16) char smc[];
    float* sm = (float*)smc;

    const int tid = threadIdx.x;
    const int lane = tid & 31, wid = tid >> 5;
    const int wm = wid >> 2, wn = wid & 3;
    const int gr = lane >> 2, gc = lane & 3;
    const int n0 = blockIdx.x * 128;
    const int m0 = blockIdx.y * 128;

    const __half* W;
    void* dst;
    int rope;
    if (MODE == 1) {
        int z = blockIdx.z;
        W = z == 0 ? w0 : (z == 1 ? w1 : w2);
        dst = z == 0 ? d0 : (z == 1 ? d1 : d2);
        rope = (z < 2);
    } else {
        W = w0;
        dst = d0;
        rope = 0;
    }

    const uint32_t smb = su32(smc);

    auto fill = [&](int s, int kc) {
        uint32_t ab = smb + (uint32_t)s * GSTAGE;
        uint32_t bb = ab + GABYTES;
#pragma unroll
        for (int it = 0; it < 4; it++) {
            int idx = tid + it * 256;
            int r = idx >> 3, c = idx & 7;
            cp16(ab + (uint32_t)(r * GASTR + c * 16),
                 A + (size_t)(m0 + r) * EMBED + kc + c * 8);
        }
#pragma unroll
        for (int it = 0; it < 4; it++) {
            int idx = tid + it * 256;
            int r = idx >> 4, c = idx & 15;
            cp16(bb + (uint32_t)(r * GBSTR + c * 16),
                 W + (size_t)(kc + r) * EMBED + n0 + c * 8);
        }
        asm volatile("cp.async.commit_group;" ::: "memory");
    };

    float acc[4][4][4];
#pragma unroll
    for (int mi = 0; mi < 4; mi++)
#pragma unroll
        for (int ni = 0; ni < 4; ni++)
#pragma unroll
            for (int r = 0; r < 4; r++) acc[mi][ni][r] = 0.f;

    fill(0, 0);

    const int a_row = (lane & 15);
    const int a_kh = (lane >> 4) * 8;
    const int b_kr = ((lane >> 3) & 1) * 8 + (lane & 7);
    const int b_nh = ((lane >> 4) & 1) * 8;

    for (int i = 0; i < NCH2; i++) {
        if (i + 1 < NCH2) {
            fill((i + 1) & 1, (i + 1) * 64);
            asm volatile("cp.async.wait_group 1;" ::: "memory");
        } else {
            asm volatile("cp.async.wait_group 0;" ::: "memory");
        }
        __syncthreads();

        const uint32_t Asb = smb + (uint32_t)(i & 1) * GSTAGE;
        const uint32_t Bsb = Asb + GABYTES;

#pragma unroll
        for (int ks = 0; ks < 4; ks++) {
            const int kb = ks * 16;
            uint32_t af[4][4], bfr[2][4];
#pragma unroll
            for (int mi = 0; mi < 4; mi++)
                ldsm4(af[mi], Asb + (uint32_t)((wm * 64 + mi * 16 + a_row) * GASTR +
                                               (kb + a_kh) * 2));
#pragma unroll
            for (int p = 0; p < 2; p++)
                ldsm4t(bfr[p], Bsb + (uint32_t)((kb + b_kr) * GBSTR +
                                                (wn * 32 + p * 16 + b_nh) * 2));
#pragma unroll
            for (int mi = 0; mi < 4; mi++)
#pragma unroll
                for (int ni = 0; ni < 4; ni++)
                    mma16(acc[mi][ni], af[mi], &bfr[ni >> 1][(ni & 1) * 2]);
        }
        __syncthreads();
    }

    // ---- epilogue ----
    if (rope) {
#pragma unroll
        for (int mi = 0; mi < 4; mi++)
#pragma unroll
            for (int h2 = 0; h2 < 2; h2++) {
                int row = m0 + wm * 64 + mi * 16 + gr + h2 * 8;
                int s = row & (SEQ - 1);
#pragma unroll
                for (int ni = 0; ni < 4; ni++) {
                    int col = n0 + wn * 32 + ni * 8 + gc * 2;
                    int p = (col & 63) >> 1;
                    float2 cs = g_rope[(size_t)s * 32 + p];
                    float e = acc[mi][ni][h2 * 2 + 0];
                    float o = acc[mi][ni][h2 * 2 + 1];
                    acc[mi][ni][h2 * 2 + 0] = e * cs.x - o * cs.y;
                    acc[mi][ni][h2 * 2 + 1] = o * cs.x + e * cs.y;
                }
            }
    }

    float* stg = sm + wid * (64 * 36);
#pragma unroll
    for (int mi = 0; mi < 4; mi++)
#pragma unroll
        for (int ni = 0; ni < 4; ni++)
#pragma unroll
            for (int h2 = 0; h2 < 2; h2++) {
                int rl = mi * 16 + gr + h2 * 8;
                int cl = ni * 8 + gc * 2;
                *(float2*)&stg[rl * 36 + cl] =
                    make_float2(acc[mi][ni][h2 * 2], acc[mi][ni][h2 * 2 + 1]);
            }
    __syncwarp();

    const int lr = lane >> 3, c4 = lane & 7;
    if (MODE == 0) {
        float* df = (float*)dst;
#pragma unroll
        for (int it = 0; it < 16; it++) {
            int rl = it * 4 + lr;
            float4 v = *(float4*)&stg[rl * 36 + c4 * 4];
            int row = m0 + wm * 64 + rl;
            *(float4*)&df[(size_t)row * EMBED + n0 + wn * 32 + c4 * 4] = v;
        }
    } else {
        __half* dh = (__half*)dst;
        const int ncol = n0 + wn * 32;
        const int h = ncol >> 6, dbase = ncol & 63;
#pragma unroll
        for (int it = 0; it < 16; it++) {
            int rl = it * 4 + lr;
            float4 v = *(float4*)&stg[rl * 36 + c4 * 4];
            int row = m0 + wm * 64 + rl;
            int b = row >> 11;
            int s = row & (SEQ - 1);
            H2U8 pk;
            pk.h[0] = __floats2half2_rn(v.x, v.y);
            pk.h[1] = __floats2half2_rn(v.z, v.w);
            *(uint2*)&dh[(((size_t)(b * HEADS + h)) * SEQ + s) * DKH + dbase + c4 * 4] = pk.u;
        }
    }
}

// ---------------------------------------------------------------------------
// fp16 tensor-core flash attention, causal, no online max, register-built P,
// merged per-column-group loop (QK(pg) -> exp -> PV(pg)); natural 80 regs.
// Q staged through V0 buffer in the prologue -> 73728 B smem;
// __launch_bounds__(256,3) -> 3 CTAs/SM (84-reg budget >= 80, no spills).
// ---------------------------------------------------------------------------
__global__ void __launch_bounds__(256, 3) flash_h(const __half* __restrict__ Q,
                                                  const __half* __restrict__ Kk,
                                                  const __half* __restrict__ V,
                                                  __half* __restrict__ Out) {
    extern __shared__ __align__(16) char fsb[];
    const int tid = threadIdx.x;
    const int lane = tid & 31, w = tid >> 5;
    const int gr = lane >> 2, gc = lane & 3;
    const int qi = gridDim.x - 1 - blockIdx.x;  // long blocks launch first
    const int bh = blockIdx.y;
    const int nt = qi + 1;  // kv tiles of 128

    const __half* Qb = Q + ((size_t)bh * SEQ + (size_t)qi * 128) * DKH;
    const __half* Kb = Kk + (size_t)bh * SEQ * DKH;
    const __half* Vb = V + (size_t)bh * SEQ * DKH;

    const uint32_t fb = su32(fsb);

    auto fillkv = [&](int buf, int j) {
        uint32_t kd = fb + (buf ? FK1B : FK0B);
        uint32_t vd = fb + (buf ? FV1B : FV0B);
        const __half* ks = Kb + (size_t)j * 128 * DKH;
        const __half* vs = Vb + (size_t)j * 128 * DKH;
#pragma unroll
        for (int it = 0; it < 4; it++) {
            int idx = tid + it * 256;
            int r = idx >> 3, c = idx & 7;
            cp16(kd + (uint32_t)(r * FST + c * 16), ks + r * 64 + c * 8);
        }
#pragma unroll
        for (int it = 0; it < 4; it++) {
            int idx = tid + it * 256;
            int r = idx >> 3, c = idx & 7;
            cp16(vd + (uint32_t)(r * FST + c * 16), vs + r * 64 + c * 8);
        }
        asm volatile("cp.async.commit_group;" ::: "memory");
    };

    // ldmatrix address components
    const int a_row = (lane & 15);
    const int a_kh = (lane >> 4) * 8;
    const int b_kr = ((lane >> 3) & 1) * 8 + (lane & 7);
    const int b_nh = ((lane >> 4) & 1) * 8;
    const int k_nr = ((lane >> 4) & 1) * 8 + (lane & 7);
    const int k_kh = ((lane >> 3) & 1) * 8;

    // ---- prologue: stage Q through the V0 buffer, grab fragments ----
    uint32_t qf[4][4];
    {
        uint32_t qd = fb + FV0B;
#pragma unroll
        for (int it = 0; it < 4; it++) {
            int idx = tid + it * 256;
            int r = idx >> 3, c = idx & 7;
            cp16(qd + (uint32_t)(r * FST + c * 16), Qb + r * 64 + c * 8);
        }
        asm volatile("cp.async.commit_group;" ::: "memory");
        asm volatile("cp.async.wait_group 0;" ::: "memory");
        __syncthreads();
#pragma unroll
        for (int ks = 0; ks < 4; ks++)
            ldsm4(qf[ks], qd + (uint32_t)((w * 16 + a_row) * FST + (ks * 16 + a_kh) * 2));
        __syncthreads();  // V0 buffer free for the KV pipeline
    }

    fillkv(0, 0);
    if (nt > 1) fillkv(1, 1);

    float liA = 0.f, liB = 0.f;
    float oacc[8][4];
#pragma unroll
    for (int n8 = 0; n8 < 8; n8++)
#pragma unroll
        for (int r = 0; r < 4; r++) oacc[n8][r] = 0.f;

    const int wrow = qi * 128 + w * 16;

    for (int j = 0; j < nt; j++) {
        if (j <= nt - 2)
            asm volatile("cp.async.wait_group 1;" ::: "memory");
        else
            asm volatile("cp.async.wait_group 0;" ::: "memory");
        __syncthreads();

        const uint32_t Ksb = fb + ((j & 1) ? FK1B : FK0B);
        const uint32_t Vsb = fb + ((j & 1) ? FV1B : FV0B);

#pragma unroll
        for (int half = 0; half < 2; half++) {
            const int colbase = j * 128 + half * 64;
            if (colbase > wrow + 15) break;  // rest of tile fully masked

            const uint32_t Kh = Ksb + (uint32_t)(half * 64 * FST);
            const uint32_t Vh = Vsb + (uint32_t)(half * 64 * FST);
            const bool diag = (colbase + 63 > wrow);

#pragma unroll
            for (int pg = 0; pg < 4; pg++) {
                if (diag && colbase + pg * 16 > wrow + 15) continue;  // masked group

                // ---- QK for this column group ----
                float s0[4] = {0.f, 0.f, 0.f, 0.f};
                float s1[4] = {0.f, 0.f, 0.f, 0.f};
#pragma unroll
                for (int ks = 0; ks < 4; ks++) {
                    uint32_t kf[4];
                    ldsm4(kf, Kh + (uint32_t)((pg * 16 + k_nr) * FST + (ks * 16 + k_kh) * 2));
                    mma16(s0, qf[ks], &kf[0]);
                    mma16(s1, qf[ks], &kf[2]);
                }

                // ---- exp + mask + pack to A-fragment ----
                float p00, p01, p02, p03, p10, p11, p12, p13;
                if (diag) {
                    int r0 = wrow + gr;
                    int c0 = colbase + pg * 16 + 2 * gc;
                    int c1 = c0 + 8;
                    p00 = (c0 > r0) ? 0.f : __expf(s0[0] * 0.125f);
                    p01 = (c0 + 1 > r0) ? 0.f : __expf(s0[1] * 0.125f);
                    p02 = (c0 > r0 + 8) ? 0.f : __expf(s0[2] * 0.125f);
                    p03 = (c0 + 1 > r0 + 8) ? 0.f : __expf(s0[3] * 0.125f);
                    p10 = (c1 > r0) ? 0.f : __expf(s1[0] * 0.125f);
                    p11 = (c1 + 1 > r0) ? 0.f : __expf(s1[1] * 0.125f);
                    p12 = (c1 > r0 + 8) ? 0.f : __expf(s1[2] * 0.125f);
                    p13 = (c1 + 1 > r0 + 8) ? 0.f : __expf(s1[3] * 0.125f);
                } else {
                    p00 = __expf(s0[0] * 0.125f);
                    p01 = __expf(s0[1] * 0.125f);
                    p02 = __expf(s0[2] * 0.125f);
                    p03 = __expf(s0[3] * 0.125f);
                    p10 = __expf(s1[0] * 0.125f);
                    p11 = __expf(s1[1] * 0.125f);
                    p12 = __expf(s1[2] * 0.125f);
                    p13 = __expf(s1[3] * 0.125f);
                }
                liA += p00 + p01 + p10 + p11;
                liB += p02 + p03 + p12 + p13;
                uint32_t pf[4];
                pf[0] = packh2(p00, p01);
                pf[1] = packh2(p02, p03);
                pf[2] = packh2(p10, p11);
                pf[3] = packh2(p12, p13);

                // ---- PV for this column group (k-chunk = pg) ----
                const int kb = pg * 16;
#pragma unroll
                for (int p = 0; p < 4; p++) {
                    uint32_t vf[4];
                    ldsm4t(vf, Vh + (uint32_t)((kb + b_kr) * FST + (p * 16 + b_nh) * 2));
                    mma16(oacc[2 * p], pf, &vf[0]);
                    mma16(oacc[2 * p + 1], pf, &vf[2]);
                }
            }
        }

        __syncthreads();  // all warps done with this KV buffer
        if (j + 2 < nt) fillkv(j & 1, j + 2);
    }

    // final row-sum reduction + normalize + write [B,S,E]
    liA += __shfl_xor_sync(0xffffffffu, liA, 1);
    liA += __shfl_xor_sync(0xffffffffu, liA, 2);
    liB += __shfl_xor_sync(0xffffffffu, liB, 1);
    liB += __shfl_xor_sync(0xffffffffu, liB, 2);

    const int b = bh >> 4, h = bh & 15;
    const int row = wrow + gr;
    float invA = 1.f / liA, invB = 1.f / liB;
    __half* o0 = Out + ((size_t)b * SEQ + row) * EMBED + h * 64;
    __half* o1 = Out + ((size_t)b * SEQ + row + 8) * EMBED + h * 64;
#pragma unroll
    for (int n8 = 0; n8 < 8; n8++) {
        *(__half2*)&o0[n8 * 8 + 2 * gc] =
            __floats2half2_rn(oacc[n8][0] * invA, oacc[n8][1] * invA);
        *(__half2*)&o1[n8 * 8 + 2 * gc] =
            __floats2half2_rn(oacc[n8][2] * invB, oacc[n8][3] * invB);
    }
}

extern "C" void kernel_launch(void* const* d_in, const int* in_sizes, int n_in,
                              void* d_out, int out_size) {
    (void)in_sizes;
    (void)n_in;
    (void)out_size;
    const float* x = (const float*)d_in[0];
    const float* wq = (const float*)d_in[1];
    const float* wk = (const float*)d_in[2];
    const float* wv = (const float*)d_in[3];
    const float* wo = (const float*)d_in[4];
    float* out = (float*)d_out;

    __half *x16, *w16, *q, *k, *v, *attn;
    cudaGetSymbolAddress((void**)&x16, g_x16);
    cudaGetSymbolAddress((void**)&w16, g_w16);
    cudaGetSymbolAddress((void**)&q, g_q);
    cudaGetSymbolAddress((void**)&k, g_k);
    cudaGetSymbolAddress((void**)&v, g_v);
    cudaGetSymbolAddress((void**)&attn, g_attn);

    cudaFuncSetAttribute(gemm_h<1>, cudaFuncAttributeMaxDynamicSharedMemorySize, GSMEM);
    cudaFuncSetAttribute(gemm_h<0>, cudaFuncAttributeMaxDynamicSharedMemorySize, GSMEM);
    cudaFuncSetAttribute(flash_h, cudaFuncAttributeMaxDynamicSharedMemorySize, FSMEMB);

    rope_table_kernel<<<SEQ * 32 / 256, 256>>>();
    cvt_fp16<<<(MTOT * EMBED / 4 + WSZ) / 256, 256>>>(x, wq, wk, wv, wo);
    gemm_h<1><<<dim3(EMBED / 128, MTOT / 128, 3), 256, GSMEM>>>(
        x16, w16, w16 + WSZ, w16 + 2 * WSZ, q, k, v);
    flash_h<<<dim3(SEQ / 128, BATCH * HEADS), 256, FSMEMB>>>(q, k, v, attn);
    gemm_h<0><<<dim3(EMBED / 128, MTOT / 128, 1), 256, GSMEM>>>(
        attn, w16 + 3 * WSZ, nullptr, nullptr, out, nullptr, nullptr);
}

// round 16
// speedup vs baseline: 1.0607x; 1.0078x over previous
#include <cuda_runtime.h>
#include <cuda_fp16.h>
#include <math.h>
#include <stdint.h>

#define EMBED 1024
#define HEADS 16
#define DKH 64
#define BATCH 2
#define SEQ 2048
#define MTOT (BATCH * SEQ)   // 4096
#define WSZ (EMBED * EMBED)  // 1048576

// ---- fp16 GEMM tiling: CTA 128x128, BK=64, 8 warps (2x4), warp tile 64x32 ----
#define NCH2 16
#define GASTR 144
#define GBSTR 272
#define GABYTES (128 * GASTR)
#define GBBYTES (64 * GBSTR)
#define GSTAGE (GABYTES + GBBYTES)
#define GSMEM 73728

// ---- flash fp16 smem (bytes): 2-stage KV tiles 128x64 halves, stride 144B.
//      Q staged through V0; 73728 B -> 3 CTAs/SM, 80-reg body. ----
#define FST 144
#define FK0B 0
#define FK1B 18432
#define FV0B 36864
#define FV1B 55296
#define FSMEMB 73728

// Scratch (allocation-free rule: __device__ globals)
__device__ __half g_x16[(size_t)MTOT * EMBED];
__device__ __half g_w16[(size_t)4 * WSZ];
__device__ __half g_q[(size_t)BATCH * HEADS * SEQ * DKH];
__device__ __half g_k[(size_t)BATCH * HEADS * SEQ * DKH];
__device__ __half g_v[(size_t)BATCH * HEADS * SEQ * DKH];
__device__ __half g_attn[(size_t)MTOT * EMBED];
__device__ float2 g_rope[(size_t)SEQ * 32];
// split-KV partials: 32 bh x 8 tiles x 2 parts x (128x64 O + 128 li)
__device__ float g_po[(size_t)32 * 8 * 2 * 128 * 64];
__device__ float g_pl[(size_t)32 * 8 * 2 * 128];

// ---------------------------------------------------------------------------
// helpers
// ---------------------------------------------------------------------------
__device__ __forceinline__ uint32_t su32(const void* p) {
    uint32_t a;
    asm("{ .reg .u64 t; cvta.to.shared.u64 t, %1; cvt.u32.u64 %0, t; }"
        : "=r"(a) : "l"(p));
    return a;
}

__device__ __forceinline__ void cp16(uint32_t dst, const void* src) {
    asm volatile("cp.async.cg.shared.global [%0], [%1], 16;" :: "r"(dst), "l"(src));
}

__device__ __forceinline__ void ldsm4(uint32_t* r, uint32_t a) {
    asm volatile("ldmatrix.sync.aligned.m8n8.x4.shared.b16 {%0,%1,%2,%3}, [%4];"
                 : "=r"(r[0]), "=r"(r[1]), "=r"(r[2]), "=r"(r[3]) : "r"(a));
}

__device__ __forceinline__ void ldsm4t(uint32_t* r, uint32_t a) {
    asm volatile("ldmatrix.sync.aligned.m8n8.x4.trans.shared.b16 {%0,%1,%2,%3}, [%4];"
                 : "=r"(r[0]), "=r"(r[1]), "=r"(r[2]), "=r"(r[3]) : "r"(a));
}

__device__ __forceinline__ void mma16(float* d, const uint32_t* a, const uint32_t* b) {
    asm volatile(
        "mma.sync.aligned.m16n8k16.row.col.f32.f16.f16.f32 "
        "{%0,%1,%2,%3}, {%4,%5,%6,%7}, {%8,%9}, {%0,%1,%2,%3};"
        : "+f"(d[0]), "+f"(d[1]), "+f"(d[2]), "+f"(d[3])
        : "r"(a[0]), "r"(a[1]), "r"(a[2]), "r"(a[3]), "r"(b[0]), "r"(b[1]));
}

__device__ __forceinline__ uint32_t packh2(float lo, float hi) {
    __half2 h = __floats2half2_rn(lo, hi);
    return *(uint32_t*)&h;
}

union H2U8 {
    __half2 h[2];
    uint2 u;
};

// ---------------------------------------------------------------------------
// prep: RoPE table + fused fp32->fp16 conversion (R11-validated form)
// ---------------------------------------------------------------------------
__global__ void rope_table_kernel() {
    int idx = blockIdx.x * 256 + threadIdx.x;
    int s = idx >> 5, p = idx & 31;
    double inv = 1.0 / pow(10000.0, (double)(2 * p) / 64.0);
    float ang = (float)s * (float)inv;
    g_rope[idx] = make_float2(cosf(ang), sinf(ang));
}

__global__ void __launch_bounds__(256) cvt_fp16(const float* __restrict__ x,
                                                const float* __restrict__ wq,
                                                const float* __restrict__ wk,
                                                const float* __restrict__ wv,
                                                const float* __restrict__ wo) {
    const int XN4 = MTOT * EMBED / 4;
    int i4 = blockIdx.x * 256 + threadIdx.x;
    const float* src;
    __half* dst;
    size_t off;
    if (i4 < XN4) {
        src = x;
        dst = g_x16;
        off = (size_t)i4 * 4;
    } else {
        int r = i4 - XN4;
        int wsel = r >> 18;  // WSZ/4 = 2^18
        int o4 = r & ((1 << 18) - 1);
        src = wsel == 0 ? wq : (wsel == 1 ? wk : (wsel == 2 ? wv : wo));
        dst = g_w16 + (size_t)wsel * WSZ;
        off = (size_t)o4 * 4;
    }
    float4 v = *(const float4*)(src + off);
    H2U8 pk;
    pk.h[0] = __floats2half2_rn(v.x, v.y);
    pk.h[1] = __floats2half2_rn(v.z, v.w);
    *(uint2*)(dst + off) = pk.u;
}

// ---------------------------------------------------------------------------
// fp16 GEMM (unchanged from R15 best)
// ---------------------------------------------------------------------------
template <int MODE>
__global__ void __launch_bounds__(256) gemm_h(const __half* __restrict__ A,
                                              const __half* __restrict__ w0,
                                              const __half* __restrict__ w1,
                                              const __half* __restrict__ w2,
                                              void* __restrict__ d0,
                                              void* __restrict__ d1,
                                              void* __restrict__ d2) {
    extern __shared__ __align__(16) char smc[];
    float* sm = (float*)smc;

    const int tid = threadIdx.x;
    const int lane = tid & 31, wid = tid >> 5;
    const int wm = wid >> 2, wn = wid & 3;
    const int gr = lane >> 2, gc = lane & 3;
    const int n0 = blockIdx.x * 128;
    const int m0 = blockIdx.y * 128;

    const __half* W;
    void* dst;
    int rope;
    if (MODE == 1) {
        int z = blockIdx.z;
        W = z == 0 ? w0 : (z == 1 ? w1 : w2);
        dst = z == 0 ? d0 : (z == 1 ? d1 : d2);
        rope = (z < 2);
    } else {
        W = w0;
        dst = d0;
        rope = 0;
    }

    const uint32_t smb = su32(smc);

    auto fill = [&](int s, int kc) {
        uint32_t ab = smb + (uint32_t)s * GSTAGE;
        uint32_t bb = ab + GABYTES;
#pragma unroll
        for (int it = 0; it < 4; it++) {
            int idx = tid + it * 256;
            int r = idx >> 3, c = idx & 7;
            cp16(ab + (uint32_t)(r * GASTR + c * 16),
                 A + (size_t)(m0 + r) * EMBED + kc + c * 8);
        }
#pragma unroll
        for (int it = 0; it < 4; it++) {
            int idx = tid + it * 256;
            int r = idx >> 4, c = idx & 15;
            cp16(bb + (uint32_t)(r * GBSTR + c * 16),
                 W + (size_t)(kc + r) * EMBED + n0 + c * 8);
        }
        asm volatile("cp.async.commit_group;" ::: "memory");
    };

    float acc[4][4][4];
#pragma unroll
    for (int mi = 0; mi < 4; mi++)
#pragma unroll
        for (int ni = 0; ni < 4; ni++)
#pragma unroll
            for (int r = 0; r < 4; r++) acc[mi][ni][r] = 0.f;

    fill(0, 0);

    const int a_row = (lane & 15);
    const int a_kh = (lane >> 4) * 8;
    const int b_kr = ((lane >> 3) & 1) * 8 + (lane & 7);
    const int b_nh = ((lane >> 4) & 1) * 8;

    for (int i = 0; i < NCH2; i++) {
        if (i + 1 < NCH2) {
            fill((i + 1) & 1, (i + 1) * 64);
            asm volatile("cp.async.wait_group 1;" ::: "memory");
        } else {
            asm volatile("cp.async.wait_group 0;" ::: "memory");
        }
        __syncthreads();

        const uint32_t Asb = smb + (uint32_t)(i & 1) * GSTAGE;
        const uint32_t Bsb = Asb + GABYTES;

#pragma unroll
        for (int ks = 0; ks < 4; ks++) {
            const int kb = ks * 16;
            uint32_t af[4][4], bfr[2][4];
#pragma unroll
            for (int mi = 0; mi < 4; mi++)
                ldsm4(af[mi], Asb + (uint32_t)((wm * 64 + mi * 16 + a_row) * GASTR +
                                               (kb + a_kh) * 2));
#pragma unroll
            for (int p = 0; p < 2; p++)
                ldsm4t(bfr[p], Bsb + (uint32_t)((kb + b_kr) * GBSTR +
                                                (wn * 32 + p * 16 + b_nh) * 2));
#pragma unroll
            for (int mi = 0; mi < 4; mi++)
#pragma unroll
                for (int ni = 0; ni < 4; ni++)
                    mma16(acc[mi][ni], af[mi], &bfr[ni >> 1][(ni & 1) * 2]);
        }
        __syncthreads();
    }

    if (rope) {
#pragma unroll
        for (int mi = 0; mi < 4; mi++)
#pragma unroll
            for (int h2 = 0; h2 < 2; h2++) {
                int row = m0 + wm * 64 + mi * 16 + gr + h2 * 8;
                int s = row & (SEQ - 1);
#pragma unroll
                for (int ni = 0; ni < 4; ni++) {
                    int col = n0 + wn * 32 + ni * 8 + gc * 2;
                    int p = (col & 63) >> 1;
                    float2 cs = g_rope[(size_t)s * 32 + p];
                    float e = acc[mi][ni][h2 * 2 + 0];
                    float o = acc[mi][ni][h2 * 2 + 1];
                    acc[mi][ni][h2 * 2 + 0] = e * cs.x - o * cs.y;
                    acc[mi][ni][h2 * 2 + 1] = o * cs.x + e * cs.y;
                }
            }
    }

    float* stg = sm + wid * (64 * 36);
#pragma unroll
    for (int mi = 0; mi < 4; mi++)
#pragma unroll
        for (int ni = 0; ni < 4; ni++)
#pragma unroll
            for (int h2 = 0; h2 < 2; h2++) {
                int rl = mi * 16 + gr + h2 * 8;
                int cl = ni * 8 + gc * 2;
                *(float2*)&stg[rl * 36 + cl] =
                    make_float2(acc[mi][ni][h2 * 2], acc[mi][ni][h2 * 2 + 1]);
            }
    __syncwarp();

    const int lr = lane >> 3, c4 = lane & 7;
    if (MODE == 0) {
        float* df = (float*)dst;
#pragma unroll
        for (int it = 0; it < 16; it++) {
            int rl = it * 4 + lr;
            float4 v = *(float4*)&stg[rl * 36 + c4 * 4];
            int row = m0 + wm * 64 + rl;
            *(float4*)&df[(size_t)row * EMBED + n0 + wn * 32 + c4 * 4] = v;
        }
    } else {
        __half* dh = (__half*)dst;
        const int ncol = n0 + wn * 32;
        const int h = ncol >> 6, dbase = ncol & 63;
#pragma unroll
        for (int it = 0; it < 16; it++) {
            int rl = it * 4 + lr;
            float4 v = *(float4*)&stg[rl * 36 + c4 * 4];
            int row = m0 + wm * 64 + rl;
            int b = row >> 11;
            int s = row & (SEQ - 1);
            H2U8 pk;
            pk.h[0] = __floats2half2_rn(v.x, v.y);
            pk.h[1] = __floats2half2_rn(v.z, v.w);
            *(uint2*)&dh[(((size_t)(b * HEADS + h)) * SEQ + s) * DKH + dbase + c4 * 4] = pk.u;
        }
    }
}

// ---------------------------------------------------------------------------
// fp16 flash attention with split-KV load balancing.
// blockIdx.x in [0,24): bx<16 -> split CTA for q-tile qi=15-(bx>>1),
// part=bx&1 (KV halves); bx>=16 -> single CTA for qi=23-bx (0..7).
// No online max -> partials combine by pure addition (combine kernel).
// ---------------------------------------------------------------------------
__global__ void __launch_bounds__(256, 3) flash_h(const __half* __restrict__ Q,
                                                  const __half* __restrict__ Kk,
                                                  const __half* __restrict__ V,
                                                  __half* __restrict__ Out) {
    extern __shared__ __align__(16) char fsb[];
    const int tid = threadIdx.x;
    const int lane = tid & 31, w = tid >> 5;
    const int gr = lane >> 2, gc = lane & 3;
    const int bx = blockIdx.x;
    const int bh = blockIdx.y;

    int qi, jb, je, part;
    if (bx < 16) {
        qi = 15 - (bx >> 1);
        part = bx & 1;
        int nt = qi + 1, half = nt >> 1;
        jb = part ? half : 0;
        je = part ? nt : half;
    } else {
        qi = 23 - bx;
        part = -1;
        jb = 0;
        je = qi + 1;
    }
    const int nj = je - jb;

    const __half* Qb = Q + ((size_t)bh * SEQ + (size_t)qi * 128) * DKH;
    const __half* Kb = Kk + (size_t)bh * SEQ * DKH;
    const __half* Vb = V + (size_t)bh * SEQ * DKH;

    const uint32_t fb = su32(fsb);

    auto fillkv = [&](int buf, int j) {
        uint32_t kd = fb + (buf ? FK1B : FK0B);
        uint32_t vd = fb + (buf ? FV1B : FV0B);
        const __half* ks = Kb + (size_t)j * 128 * DKH;
        const __half* vs = Vb + (size_t)j * 128 * DKH;
#pragma unroll
        for (int it = 0; it < 4; it++) {
            int idx = tid + it * 256;
            int r = idx >> 3, c = idx & 7;
            cp16(kd + (uint32_t)(r * FST + c * 16), ks + r * 64 + c * 8);
        }
#pragma unroll
        for (int it = 0; it < 4; it++) {
            int idx = tid + it * 256;
            int r = idx >> 3, c = idx & 7;
            cp16(vd + (uint32_t)(r * FST + c * 16), vs + r * 64 + c * 8);
        }
        asm volatile("cp.async.commit_group;" ::: "memory");
    };

    // ldmatrix address components
    const int a_row = (lane & 15);
    const int a_kh = (lane >> 4) * 8;
    const int b_kr = ((lane >> 3) & 1) * 8 + (lane & 7);
    const int b_nh = ((lane >> 4) & 1) * 8;
    const int k_nr = ((lane >> 4) & 1) * 8 + (lane & 7);
    const int k_kh = ((lane >> 3) & 1) * 8;

    // ---- prologue: stage Q through the V0 buffer, grab fragments ----
    uint32_t qf[4][4];
    {
        uint32_t qd = fb + FV0B;
#pragma unroll
        for (int it = 0; it < 4; it++) {
            int idx = tid + it * 256;
            int r = idx >> 3, c = idx & 7;
            cp16(qd + (uint32_t)(r * FST + c * 16), Qb + r * 64 + c * 8);
        }
        asm volatile("cp.async.commit_group;" ::: "memory");
        asm volatile("cp.async.wait_group 0;" ::: "memory");
        __syncthreads();
#pragma unroll
        for (int ks = 0; ks < 4; ks++)
            ldsm4(qf[ks], qd + (uint32_t)((w * 16 + a_row) * FST + (ks * 16 + a_kh) * 2));
        __syncthreads();  // V0 buffer free for the KV pipeline
    }

    fillkv(0, jb);
    if (nj > 1) fillkv(1, jb + 1);

    float liA = 0.f, liB = 0.f;
    float oacc[8][4];
#pragma unroll
    for (int n8 = 0; n8 < 8; n8++)
#pragma unroll
        for (int r = 0; r < 4; r++) oacc[n8][r] = 0.f;

    const int wrow = qi * 128 + w * 16;

    for (int jj = 0; jj < nj; jj++) {
        const int j = jb + jj;
        if (jj <= nj - 2)
            asm volatile("cp.async.wait_group 1;" ::: "memory");
        else
            asm volatile("cp.async.wait_group 0;" ::: "memory");
        __syncthreads();

        const uint32_t Ksb = fb + ((jj & 1) ? FK1B : FK0B);
        const uint32_t Vsb = fb + ((jj & 1) ? FV1B : FV0B);

#pragma unroll
        for (int half = 0; half < 2; half++) {
            const int colbase = j * 128 + half * 64;
            if (colbase > wrow + 15) break;  // rest of tile fully masked

            const uint32_t Kh = Ksb + (uint32_t)(half * 64 * FST);
            const uint32_t Vh = Vsb + (uint32_t)(half * 64 * FST);
            const bool diag = (colbase + 63 > wrow);

#pragma unroll
            for (int pg = 0; pg < 4; pg++) {
                if (diag && colbase + pg * 16 > wrow + 15) continue;

                float s0[4] = {0.f, 0.f, 0.f, 0.f};
                float s1[4] = {0.f, 0.f, 0.f, 0.f};
#pragma unroll
                for (int ks = 0; ks < 4; ks++) {
                    uint32_t kf[4];
                    ldsm4(kf, Kh + (uint32_t)((pg * 16 + k_nr) * FST + (ks * 16 + k_kh) * 2));
                    mma16(s0, qf[ks], &kf[0]);
                    mma16(s1, qf[ks], &kf[2]);
                }

                float p00, p01, p02, p03, p10, p11, p12, p13;
                if (diag) {
                    int r0 = wrow + gr;
                    int c0 = colbase + pg * 16 + 2 * gc;
                    int c1 = c0 + 8;
                    p00 = (c0 > r0) ? 0.f : __expf(s0[0] * 0.125f);
                    p01 = (c0 + 1 > r0) ? 0.f : __expf(s0[1] * 0.125f);
                    p02 = (c0 > r0 + 8) ? 0.f : __expf(s0[2] * 0.125f);
                    p03 = (c0 + 1 > r0 + 8) ? 0.f : __expf(s0[3] * 0.125f);
                    p10 = (c1 > r0) ? 0.f : __expf(s1[0] * 0.125f);
                    p11 = (c1 + 1 > r0) ? 0.f : __expf(s1[1] * 0.125f);
                    p12 = (c1 > r0 + 8) ? 0.f : __expf(s1[2] * 0.125f);
                    p13 = (c1 + 1 > r0 + 8) ? 0.f : __expf(s1[3] * 0.125f);
                } else {
                    p00 = __expf(s0[0] * 0.125f);
                    p01 = __expf(s0[1] * 0.125f);
                    p02 = __expf(s0[2] * 0.125f);
                    p03 = __expf(s0[3] * 0.125f);
                    p10 = __expf(s1[0] * 0.125f);
                    p11 = __expf(s1[1] * 0.125f);
                    p12 = __expf(s1[2] * 0.125f);
                    p13 = __expf(s1[3] * 0.125f);
                }
                liA += p00 + p01 + p10 + p11;
                liB += p02 + p03 + p12 + p13;
                uint32_t pf[4];
                pf[0] = packh2(p00, p01);
                pf[1] = packh2(p02, p03);
                pf[2] = packh2(p10, p11);
                pf[3] = packh2(p12, p13);

                const int kb = pg * 16;
#pragma unroll
                for (int p = 0; p < 4; p++) {
                    uint32_t vf[4];
                    ldsm4t(vf, Vh + (uint32_t)((kb + b_kr) * FST + (p * 16 + b_nh) * 2));
                    mma16(oacc[2 * p], pf, &vf[0]);
                    mma16(oacc[2 * p + 1], pf, &vf[2]);
                }
            }
        }

        __syncthreads();
        if (jj + 2 < nj) fillkv(jj & 1, jb + jj + 2);
    }

    // row-sum reduction across the quad
    liA += __shfl_xor_sync(0xffffffffu, liA, 1);
    liA += __shfl_xor_sync(0xffffffffu, liA, 2);
    liB += __shfl_xor_sync(0xffffffffu, liB, 1);
    liB += __shfl_xor_sync(0xffffffffu, liB, 2);

    const int r0l = w * 16 + gr;  // local rows r0l, r0l+8
    if (part < 0) {
        // single CTA: normalize + write fp16 attn
        const int b = bh >> 4, h = bh & 15;
        const int row = qi * 128 + r0l;
        float invA = 1.f / liA, invB = 1.f / liB;
        __half* o0 = Out + ((size_t)b * SEQ + row) * EMBED + h * 64;
        __half* o1 = Out + ((size_t)b * SEQ + row + 8) * EMBED + h * 64;
#pragma unroll
        for (int n8 = 0; n8 < 8; n8++) {
            *(__half2*)&o0[n8 * 8 + 2 * gc] =
                __floats2half2_rn(oacc[n8][0] * invA, oacc[n8][1] * invA);
            *(__half2*)&o1[n8 * 8 + 2 * gc] =
                __floats2half2_rn(oacc[n8][2] * invB, oacc[n8][3] * invB);
        }
    } else {
        // split CTA: write unnormalized fp32 partials + li
        size_t tidx = ((size_t)bh * 8 + (qi - 8)) * 2 + part;
        float* O = g_po + tidx * (128 * 64);
#pragma unroll
        for (int n8 = 0; n8 < 8; n8++) {
            *(float2*)&O[r0l * 64 + n8 * 8 + 2 * gc] =
                make_float2(oacc[n8][0], oacc[n8][1]);
            *(float2*)&O[(r0l + 8) * 64 + n8 * 8 + 2 * gc] =
                make_float2(oacc[n8][2], oacc[n8][3]);
        }
        if (gc == 0) {
            g_pl[tidx * 128 + r0l] = liA;
            g_pl[tidx * 128 + r0l + 8] = liB;
        }
    }
}

// ---------------------------------------------------------------------------
// combine: for split q-tiles (qi 8..15), sum the two partials, normalize,
// emit fp16 attn. 256 blocks (bh x tile), 256 threads, coalesced on cols.
// ---------------------------------------------------------------------------
__global__ void __launch_bounds__(256) combine_k(__half* __restrict__ Out) {
    const int blk = blockIdx.x;  // bh*8 + t8
    const int bh = blk >> 3, t8 = blk & 7;
    const int qi = 8 + t8;
    const int b = bh >> 4, h = bh & 15;
    const float* p0 = g_po + (size_t)(blk * 2) * (128 * 64);
    const float* p1 = p0 + 128 * 64;
    const float* l0 = g_pl + (size_t)(blk * 2) * 128;
    const float* l1 = l0 + 128;

    const int t = threadIdx.x;
    const int c = t & 63, rg = t >> 6;
#pragma unroll 4
    for (int k = 0; k < 32; k++) {
        int r = rg * 32 + k;
        float li = l0[r] + l1[r];
        float o = (p0[r * 64 + c] + p1[r * 64 + c]) / li;
        int s = qi * 128 + r;
        Out[((size_t)b * SEQ + s) * EMBED + h * 64 + c] = __float2half(o);
    }
}

extern "C" void kernel_launch(void* const* d_in, const int* in_sizes, int n_in,
                              void* d_out, int out_size) {
    (void)in_sizes;
    (void)n_in;
    (void)out_size;
    const float* x = (const float*)d_in[0];
    const float* wq = (const float*)d_in[1];
    const float* wk = (const float*)d_in[2];
    const float* wv = (const float*)d_in[3];
    const float* wo = (const float*)d_in[4];
    float* out = (float*)d_out;

    __half *x16, *w16, *q, *k, *v, *attn;
    cudaGetSymbolAddress((void**)&x16, g_x16);
    cudaGetSymbolAddress((void**)&w16, g_w16);
    cudaGetSymbolAddress((void**)&q, g_q);
    cudaGetSymbolAddress((void**)&k, g_k);
    cudaGetSymbolAddress((void**)&v, g_v);
    cudaGetSymbolAddress((void**)&attn, g_attn);

    cudaFuncSetAttribute(gemm_h<1>, cudaFuncAttributeMaxDynamicSharedMemorySize, GSMEM);
    cudaFuncSetAttribute(gemm_h<0>, cudaFuncAttributeMaxDynamicSharedMemorySize, GSMEM);
    cudaFuncSetAttribute(flash_h, cudaFuncAttributeMaxDynamicSharedMemorySize, FSMEMB);

    rope_table_kernel<<<SEQ * 32 / 256, 256>>>();
    cvt_fp16<<<(MTOT * EMBED / 4 + WSZ) / 256, 256>>>(x, wq, wk, wv, wo);
    gemm_h<1><<<dim3(EMBED / 128, MTOT / 128, 3), 256, GSMEM>>>(
        x16, w16, w16 + WSZ, w16 + 2 * WSZ, q, k, v);
    flash_h<<<dim3(24, BATCH * HEADS), 256, FSMEMB>>>(q, k, v, attn);
    combine_k<<<256, 256>>>(attn);
    gemm_h<0><<<dim3(EMBED / 128, MTOT / 128, 1), 256, GSMEM>>>(
        attn, w16 + 3 * WSZ, nullptr, nullptr, out, nullptr, nullptr);
}